// round 1
// baseline (speedup 1.0000x reference)
#include <cuda_runtime.h>
#include <math.h>

// ---------------------------------------------------------------------------
// SolutionCalculatorSurface — fused per-node-tile MLP chain.
// CTA = 9 nodes (63 rows of the M = N*7 GEMM, padded to 64), 256 threads.
// Layers (per v): L1 (7->256), L2 (256->256), L3 (256->256 + per-node ctx GEMM
// 160->256 + global cst3), L4 (256->128), L5 (128->1) + inv-dist reduction.
// Inner GEMMs use packed fma.rn.f32x2 (2 FMA/instr) — 128 FMA/cyc/SM ceiling.
// ---------------------------------------------------------------------------

constexpr int V_   = 4;
constexpr int NK   = 6;
constexpr int PP   = 7;
constexpr int NPC  = 9;     // nodes per CTA
constexpr int ROWS_= 63;    // NPC * PP
constexpr int MM   = 64;    // padded rows
constexpr int NTHREADS = 256;
constexpr int H1_  = 256;
constexpr int H2_  = 128;
constexpr int DCTX = 160;   // enc_node(32) + enc_g(128)

// shared layout (float offsets)
constexpr int OFF_SVOL = 0;                    // 64*8   = 512
constexpr int OFF_CTX  = 512;                  // 9*160  = 1440
constexpr int OFF_INVD = 1952;                 // 9*8    = 72
constexpr int OFF_DSUM = 2024;                 // 9 (+pad)
constexpr int OFF_CTXP = 2048;                 // 9*256  = 2304
constexpr int OFF_AROW = 4352;                 // 64
constexpr int OFF_W3   = 4416;                 // 128
constexpr int OFF_ACTA = 4544;                 // 64*256 = 16384
constexpr int OFF_ACTB = 20928;                // 64*256 = 16384
constexpr int OFF_WT   = 37312;                // 32*256 = 8192
constexpr int SMEM_FLOATS = 45504;
constexpr int SMEM_BYTES  = SMEM_FLOATS * 4;   // 182016 B

__device__ float g_cst3[V_][H1_];

// --------------------------- packed f32x2 FMA ------------------------------
__device__ __forceinline__ float2 ffma2(float2 d, float2 a, float2 b) {
    unsigned long long dd = *reinterpret_cast<unsigned long long*>(&d);
    unsigned long long aa = *reinterpret_cast<unsigned long long*>(&a);
    unsigned long long bb = *reinterpret_cast<unsigned long long*>(&b);
    asm("fma.rn.f32x2 %0, %1, %2, %0;" : "+l"(dd) : "l"(aa), "l"(bb));
    return *reinterpret_cast<float2*>(&dd);
}

// ------------------------- precompute (global ctx) -------------------------
// param_enc = relu(p @ param_W + param_b); cst3[v] = param_enc @ agg_W1[v][416:448] + agg_b1[v]
__global__ void precompute_kernel(
    const float* __restrict__ gpv, const float* __restrict__ gpr,
    const float* __restrict__ param_W, const float* __restrict__ param_b,
    const float* __restrict__ agg_W1, const float* __restrict__ agg_b1)
{
    __shared__ float pe[32];
    const int t = threadIdx.x;
    const float p0 = gpv[0] / gpr[0];
    const float p1 = gpv[1] / gpr[1];
    if (t < 32) {
        float s = param_b[t] + p0 * param_W[t] + p1 * param_W[32 + t];
        pe[t] = fmaxf(s, 0.f);
    }
    __syncthreads();
    for (int idx = t; idx < V_ * H1_; idx += blockDim.x) {
        const int v = idx >> 8, c = idx & 255;
        const float* W = agg_W1 + ((size_t)v * 448 + 416) * H1_ + c;
        float s = agg_b1[v * H1_ + c];
#pragma unroll
        for (int k = 0; k < 32; k++) s += pe[k] * W[(size_t)k * H1_];
        g_cst3[v][c] = s;
    }
}

// --------------------------- fused GEMM layer -------------------------------
// dst[64][NCOLS] = relu(src[64][256] @ Wg[256][NCOLS] + (bias | ctxp[node])).
// MODE 0: global bias. MODE 1: per-node ctxp (cst3 already folded in).
template <int NCOLS, int MODE>
__device__ __forceinline__ void gemm_layer(
    float* sm, const float* __restrict__ src, float* __restrict__ dst,
    const float* __restrict__ Wg, const float* __restrict__ bias)
{
    constexpr int CPT = NCOLS / 16;   // cols per thread: 16 or 8
    constexpr int NC2 = CPT / 2;      // float2 accumulators per row
    constexpr int NI  = CPT / 4;      // float4 weight chunks per k
    const int t   = threadIdx.x;
    const int tx  = t & 15;
    const int ty  = t >> 4;
    const int row0 = ty * 4;
    float* wt = sm + OFF_WT;
    const float* ctxp = sm + OFF_CTXP;

    float2 acc[4][NC2];
#pragma unroll
    for (int r = 0; r < 4; r++)
#pragma unroll
        for (int i = 0; i < NC2; i++) acc[r][i] = make_float2(0.f, 0.f);

#pragma unroll 1
    for (int kt = 0; kt < 8; kt++) {
        __syncthreads();
        {
            const float4* g4 = reinterpret_cast<const float4*>(Wg + (size_t)kt * 32 * NCOLS);
            float4* w4 = reinterpret_cast<float4*>(wt);
            constexpr int NLD = (32 * NCOLS / 4) / NTHREADS;  // 8 or 4
#pragma unroll
            for (int i = 0; i < NLD; i++) w4[t + i * NTHREADS] = __ldg(g4 + t + i * NTHREADS);
        }
        __syncthreads();
        const float* s0 = src + kt * 32;
#pragma unroll 8
        for (int k = 0; k < 32; k++) {
            float4 q[NI];
#pragma unroll
            for (int i = 0; i < NI; i++)
                q[i] = *reinterpret_cast<const float4*>(wt + k * NCOLS + tx * 4 + i * 64);
#pragma unroll
            for (int r = 0; r < 4; r++) {
                const float a = s0[(row0 + r) * H1_ + k];
                const float2 aa = make_float2(a, a);
#pragma unroll
                for (int i = 0; i < NI; i++) {
                    acc[r][2 * i + 0] = ffma2(acc[r][2 * i + 0], aa, make_float2(q[i].x, q[i].y));
                    acc[r][2 * i + 1] = ffma2(acc[r][2 * i + 1], aa, make_float2(q[i].z, q[i].w));
                }
            }
        }
    }
    // epilogue: bias/ctx add + relu, write to dst
#pragma unroll
    for (int r = 0; r < 4; r++) {
        const int row = row0 + r;
        int node = row / 7; if (node > 8) node = 8;   // pad row clamp
#pragma unroll
        for (int i = 0; i < NI; i++) {
            const int col = tx * 4 + i * 64;
            float4 add;
            if constexpr (MODE == 0)
                add = __ldg(reinterpret_cast<const float4*>(bias + col));
            else
                add = *reinterpret_cast<const float4*>(ctxp + node * H1_ + col);
            const float2 a0 = acc[r][2 * i], a1 = acc[r][2 * i + 1];
            float4 o;
            o.x = fmaxf(a0.x + add.x, 0.f);
            o.y = fmaxf(a0.y + add.y, 0.f);
            o.z = fmaxf(a1.x + add.z, 0.f);
            o.w = fmaxf(a1.y + add.w, 0.f);
            *reinterpret_cast<float4*>(dst + row * H1_ + col) = o;
        }
    }
}

// ------------------------------ main kernel --------------------------------
__global__ void __launch_bounds__(NTHREADS, 1)
surface_kernel(
    const float* __restrict__ centers,       const float* __restrict__ enc_g,
    const float* __restrict__ enc_node,      const float* __restrict__ neighbors,
    const float* __restrict__ normals,       const float* __restrict__ neigh_normals,
    const float* __restrict__ areas,         const float* __restrict__ neigh_areas,
    const float* __restrict__ basis_W1,      const float* __restrict__ basis_b1,
    const float* __restrict__ basis_W2,      const float* __restrict__ basis_b2,
    const float* __restrict__ agg_W1,
    const float* __restrict__ agg_W2,        const float* __restrict__ agg_b2,
    const float* __restrict__ agg_W3,        const float* __restrict__ agg_b3,
    float* __restrict__ out, const int n_nodes)
{
    extern __shared__ float sm[];
    const int t    = threadIdx.x;
    const int base = blockIdx.x * NPC;

    float* svol = sm + OFF_SVOL;
    float* ctx  = sm + OFF_CTX;
    float* invd = sm + OFF_INVD;
    float* dsum = sm + OFF_DSUM;
    float* ctxp = sm + OFF_CTXP;
    float* arow = sm + OFF_AROW;
    float* w3s  = sm + OFF_W3;
    float* actA = sm + OFF_ACTA;
    float* actB = sm + OFF_ACTB;

    // ---- build vol rows (row = nl*7 + p; p==0 center, p>0 neighbor+1e-6) ----
    if (t < MM) {
        float f[8] = {0.f,0.f,0.f,0.f,0.f,0.f,0.f,0.f};
        const int nl = t / PP, p = t % PP;
        const int node = base + nl;
        if (t < ROWS_ && node < n_nodes) {
            if (p == 0) {
                f[0] = centers[node*3+0]; f[1] = centers[node*3+1]; f[2] = centers[node*3+2];
                f[3] = normals[node*3+0]; f[4] = normals[node*3+1]; f[5] = normals[node*3+2];
                f[6] = logf(areas[node]) * 0.1f;
            } else {
                const int j  = p - 1;
                const int nb = node * NK + j;
                f[0] = neighbors[nb*3+0] + 1e-6f;      f[1] = neighbors[nb*3+1] + 1e-6f;
                f[2] = neighbors[nb*3+2] + 1e-6f;
                f[3] = neigh_normals[nb*3+0] + 1e-6f;  f[4] = neigh_normals[nb*3+1] + 1e-6f;
                f[5] = neigh_normals[nb*3+2] + 1e-6f;
                f[6] = logf(neigh_areas[nb]) * 0.1f + 1e-6f;
            }
        }
#pragma unroll
        for (int q = 0; q < 8; q++) svol[t*8 + q] = f[q];
    }
    // ---- per-node context (enc_node ++ enc_g) ----
    for (int idx = t; idx < NPC * DCTX; idx += NTHREADS) {
        const int nl = idx / DCTX, fi = idx % DCTX;
        const int node = base + nl;
        float vl = 0.f;
        if (node < n_nodes)
            vl = (fi < 32) ? enc_node[node*32 + fi] : enc_g[node*128 + (fi - 32)];
        ctx[nl*DCTX + fi] = vl;
    }
    __syncthreads();
    // ---- inverse distances (over all 7 features, matching reference) ----
    if (t < NPC * NK) {
        const int nl = t / NK, j = t % NK;
        float d2 = 0.f;
#pragma unroll
        for (int q = 0; q < 7; q++) {
            const float d = svol[(nl*7)*8 + q] - svol[(nl*7 + 1 + j)*8 + q];
            d2 += d * d;
        }
        invd[nl*8 + j] = 1.f / sqrtf(d2);
    }
    __syncthreads();
    if (t < NPC) {
        float s = 0.f;
#pragma unroll
        for (int j = 0; j < NK; j++) s += invd[t*8 + j];
        dsum[t] = s;
    }

    for (int v = 0; v < V_; v++) {
        // ---- L1: h = relu(vol @ basis_W1 + b1), K=7 ----
        {
            const int col = t;
            const float* W1 = basis_W1 + (size_t)v * 7 * H1_ + col;
            float w[7];
#pragma unroll
            for (int k = 0; k < 7; k++) w[k] = __ldg(W1 + k * H1_);
            const float b = __ldg(basis_b1 + v * H1_ + col);
#pragma unroll 4
            for (int r = 0; r < MM; r++) {
                float s = b;
#pragma unroll
                for (int k = 0; k < 7; k++) s += svol[r*8 + k] * w[k];
                actA[r*H1_ + col] = fmaxf(s, 0.f);
            }
        }
        // ---- per-node ctx GEMM: ctxp[nl] = ctx[nl] @ agg_W1[256:416] + cst3 ----
        {
            const int col = t;
            float acc[NPC];
#pragma unroll
            for (int nl = 0; nl < NPC; nl++) acc[nl] = 0.f;
            const float* Wc = agg_W1 + ((size_t)v * 448 + 256) * H1_ + col;
#pragma unroll 4
            for (int k = 0; k < DCTX; k++) {
                const float wv = __ldg(Wc + (size_t)k * H1_);
#pragma unroll
                for (int nl = 0; nl < NPC; nl++) acc[nl] += ctx[nl*DCTX + k] * wv;
            }
            const float cst = g_cst3[v][col];
#pragma unroll
            for (int nl = 0; nl < NPC; nl++) ctxp[nl*H1_ + col] = acc[nl] + cst;
        }
        // ---- L2: basis = relu(h @ basis_W2 + b2) ----
        gemm_layer<256, 0>(sm, actA, actB, basis_W2 + (size_t)v * H1_ * H1_, basis_b2 + v * H1_);
        // ---- L3: a1 = relu(basis @ agg_W1[0:256] + ctxp[node]) ----
        gemm_layer<256, 1>(sm, actB, actA, agg_W1 + (size_t)v * 448 * H1_, nullptr);
        // ---- L4: a2 = relu(a1 @ agg_W2 + b4) ----
        gemm_layer<128, 0>(sm, actA, actB, agg_W2 + (size_t)v * H1_ * H2_, agg_b2 + v * H2_);
        // ---- L5: per-row scalar head (rotated index -> no bank conflicts) ----
        if (t < H2_) w3s[t] = __ldg(agg_W3 + v * H2_ + t);
        __syncthreads();
        if (t < MM) {
            const int row = t;
            float s = __ldg(agg_b3 + v);
#pragma unroll 8
            for (int k = 0; k < H2_; k++) {
                const int kp = (k + row) & (H2_ - 1);
                s += actB[row*H1_ + kp] * w3s[kp];
            }
            arow[row] = s;
        }
        __syncthreads();
        // ---- inverse-distance aggregation + output ----
        if (t < NPC) {
            const int node = base + t;
            if (node < n_nodes) {
                const float c = arow[t*7];
                float s = 0.f;
#pragma unroll
                for (int j = 0; j < NK; j++) s += arow[t*7 + 1 + j] * invd[t*8 + j];
                out[node * V_ + v] = 0.5f * c + 0.5f * s / dsum[t];
            }
        }
        __syncthreads();
    }
}

// ------------------------------ launcher ------------------------------------
extern "C" void kernel_launch(void* const* d_in, const int* in_sizes, int n_in,
                              void* d_out, int out_size)
{
    const float* centers       = (const float*)d_in[0];
    const float* enc_g         = (const float*)d_in[1];
    const float* enc_node      = (const float*)d_in[2];
    const float* neighbors     = (const float*)d_in[3];
    const float* normals       = (const float*)d_in[4];
    const float* neigh_normals = (const float*)d_in[5];
    const float* areas         = (const float*)d_in[6];
    const float* neigh_areas   = (const float*)d_in[7];
    const float* gpv           = (const float*)d_in[8];
    const float* gpr           = (const float*)d_in[9];
    const float* param_W       = (const float*)d_in[10];
    const float* param_b       = (const float*)d_in[11];
    const float* basis_W1      = (const float*)d_in[12];
    const float* basis_b1      = (const float*)d_in[13];
    const float* basis_W2      = (const float*)d_in[14];
    const float* basis_b2      = (const float*)d_in[15];
    const float* agg_W1        = (const float*)d_in[16];
    const float* agg_b1        = (const float*)d_in[17];
    const float* agg_W2        = (const float*)d_in[18];
    const float* agg_b2        = (const float*)d_in[19];
    const float* agg_W3        = (const float*)d_in[20];
    const float* agg_b3        = (const float*)d_in[21];
    float* out = (float*)d_out;

    const int n_nodes = in_sizes[0] / 3;                 // 50000
    const int grid = (n_nodes + NPC - 1) / NPC;          // 5556

    cudaFuncSetAttribute(surface_kernel,
                         cudaFuncAttributeMaxDynamicSharedMemorySize, SMEM_BYTES);

    precompute_kernel<<<1, 256>>>(gpv, gpr, param_W, param_b, agg_W1, agg_b1);
    surface_kernel<<<grid, NTHREADS, SMEM_BYTES>>>(
        centers, enc_g, enc_node, neighbors, normals, neigh_normals,
        areas, neigh_areas,
        basis_W1, basis_b1, basis_W2, basis_b2,
        agg_W1, agg_W2, agg_b2, agg_W3, agg_b3,
        out, n_nodes);
}

// round 2
// speedup vs baseline: 1.1039x; 1.1039x over previous
#include <cuda_runtime.h>
#include <math.h>

// ---------------------------------------------------------------------------
// SolutionCalculatorSurface — fused per-node-tile MLP chain, round 2.
// Changes vs R1:
//  * thread mapping swapped (tx=t>>4) -> weight LDS broadcast (1 wavefront)
//  * activations stored transposed [k][row], padded stride 68 -> one LDS.128
//    per thread per k (2 wavefronts) instead of 4 scalar LDS
//  * weight tiles double-buffered via cp.async (latency hidden)
// ---------------------------------------------------------------------------

constexpr int V_   = 4;
constexpr int NK   = 6;
constexpr int PP   = 7;
constexpr int NPC  = 9;     // nodes per CTA
constexpr int ROWS_= 63;    // NPC * PP
constexpr int MM   = 64;    // padded rows
constexpr int NTHREADS = 256;
constexpr int H1_  = 256;
constexpr int H2_  = 128;
constexpr int DCTX = 160;   // enc_node(32) + enc_g(128)
constexpr int RS   = 68;    // padded row stride of transposed activations

// shared layout (float offsets)
constexpr int OFF_SVOL = 0;        // 512
constexpr int OFF_CTX  = 512;      // 1440
constexpr int OFF_INVD = 1952;     // 72
constexpr int OFF_DSUM = 2024;     // 24 (pad)
constexpr int OFF_CTXP = 2048;     // 2304
constexpr int OFF_AROW = 4352;     // 64
constexpr int OFF_W3   = 4416;     // 128
constexpr int OFF_ACTA = 4544;     // 256*68 = 17408
constexpr int OFF_ACTB = 21952;    // 17408
constexpr int OFF_WT   = 39360;    // 2 * 32*256 = 16384
constexpr int SMEM_FLOATS = 55744;
constexpr int SMEM_BYTES  = SMEM_FLOATS * 4;   // 222976 B

__device__ float g_cst3[V_][H1_];

// --------------------------- packed f32x2 FMA ------------------------------
__device__ __forceinline__ float2 ffma2(float2 d, float2 a, float2 b) {
    unsigned long long dd = *reinterpret_cast<unsigned long long*>(&d);
    unsigned long long aa = *reinterpret_cast<unsigned long long*>(&a);
    unsigned long long bb = *reinterpret_cast<unsigned long long*>(&b);
    asm("fma.rn.f32x2 %0, %1, %2, %0;" : "+l"(dd) : "l"(aa), "l"(bb));
    return *reinterpret_cast<float2*>(&dd);
}

__device__ __forceinline__ void cp_async16(float* smem_dst, const float4* gsrc) {
    unsigned saddr = (unsigned)__cvta_generic_to_shared(smem_dst);
    asm volatile("cp.async.cg.shared.global [%0], [%1], 16;\n"
                 :: "r"(saddr), "l"(gsrc));
}
__device__ __forceinline__ void cp_async_commit() {
    asm volatile("cp.async.commit_group;\n" ::);
}
__device__ __forceinline__ void cp_async_wait0() {
    asm volatile("cp.async.wait_group 0;\n" ::);
}

// ------------------------- precompute (global ctx) -------------------------
__global__ void precompute_kernel(
    const float* __restrict__ gpv, const float* __restrict__ gpr,
    const float* __restrict__ param_W, const float* __restrict__ param_b,
    const float* __restrict__ agg_W1, const float* __restrict__ agg_b1)
{
    __shared__ float pe[32];
    const int t = threadIdx.x;
    const float p0 = gpv[0] / gpr[0];
    const float p1 = gpv[1] / gpr[1];
    if (t < 32) {
        float s = param_b[t] + p0 * param_W[t] + p1 * param_W[32 + t];
        pe[t] = fmaxf(s, 0.f);
    }
    __syncthreads();
    for (int idx = t; idx < V_ * H1_; idx += blockDim.x) {
        const int v = idx >> 8, c = idx & 255;
        const float* W = agg_W1 + ((size_t)v * 448 + 416) * H1_ + c;
        float s = agg_b1[v * H1_ + c];
#pragma unroll
        for (int k = 0; k < 32; k++) s += pe[k] * W[(size_t)k * H1_];
        g_cst3[v][c] = s;
    }
}

// --------------------------- fused GEMM layer -------------------------------
// dst_t[col][row] = relu(src_t(.)[256][64] GEMM Wg[256][NCOLS] + bias|ctxp).
// src_t / dst_t are [k][row] with row stride RS. MODE 0: bias, MODE 1: ctxp.
template <int NCOLS, int MODE>
__device__ __forceinline__ void gemm_layer(
    float* sm, const float* __restrict__ src_t, float* __restrict__ dst_t,
    const float* __restrict__ Wg, const float* __restrict__ bias)
{
    constexpr int NI   = NCOLS / 64;          // float4 weight chunks (4 or 2)
    constexpr int TILE = 32 * NCOLS;          // floats per k-tile
    constexpr int NLD  = (TILE / 4) / NTHREADS;
    const int t    = threadIdx.x;
    const int tx   = t >> 4;                  // col group 0..15
    const int ty   = t & 15;                  // row group 0..15
    const int row0 = ty * 4;
    float* wt = sm + OFF_WT;
    const float* ctxp = sm + OFF_CTXP;

    float2 acc[4][2 * NI];
#pragma unroll
    for (int r = 0; r < 4; r++)
#pragma unroll
        for (int i = 0; i < 2 * NI; i++) acc[r][i] = make_float2(0.f, 0.f);

    // prefetch tile 0
    {
        const float4* g4 = reinterpret_cast<const float4*>(Wg);
#pragma unroll
        for (int i = 0; i < NLD; i++)
            cp_async16(wt + (t + i * NTHREADS) * 4, g4 + t + i * NTHREADS);
        cp_async_commit();
    }

#pragma unroll 1
    for (int kt = 0; kt < 8; kt++) {
        cp_async_wait0();
        __syncthreads();
        if (kt + 1 < 8) {
            const float4* g4 = reinterpret_cast<const float4*>(Wg + (size_t)(kt + 1) * TILE);
            float* wb = wt + ((kt + 1) & 1) * TILE;
#pragma unroll
            for (int i = 0; i < NLD; i++)
                cp_async16(wb + (t + i * NTHREADS) * 4, g4 + t + i * NTHREADS);
            cp_async_commit();
        }
        const float* wb = wt + (kt & 1) * TILE;
        const float* ap = src_t + (size_t)(kt * 32) * RS + row0;
#pragma unroll 4
        for (int k = 0; k < 32; k++) {
            const float4 av = *reinterpret_cast<const float4*>(ap + k * RS);
            float4 q[NI];
#pragma unroll
            for (int i = 0; i < NI; i++)
                q[i] = *reinterpret_cast<const float4*>(wb + k * NCOLS + tx * 4 + i * 64);
            const float ar[4] = {av.x, av.y, av.z, av.w};
#pragma unroll
            for (int r = 0; r < 4; r++) {
                const float2 aa = make_float2(ar[r], ar[r]);
#pragma unroll
                for (int i = 0; i < NI; i++) {
                    acc[r][2 * i + 0] = ffma2(acc[r][2 * i + 0], aa, make_float2(q[i].x, q[i].y));
                    acc[r][2 * i + 1] = ffma2(acc[r][2 * i + 1], aa, make_float2(q[i].z, q[i].w));
                }
            }
        }
    }

    // epilogue: bias/ctx add + relu, write transposed (per-col float4 of rows)
    int nidx[4];
#pragma unroll
    for (int r = 0; r < 4; r++) {
        int node = (row0 + r) / 7; if (node > 8) node = 8;
        nidx[r] = node;
    }
#pragma unroll
    for (int i = 0; i < NI; i++) {
        const int col0 = tx * 4 + i * 64;
        float4 bv;
        if constexpr (MODE == 0)
            bv = __ldg(reinterpret_cast<const float4*>(bias + col0));
#pragma unroll
        for (int c = 0; c < 4; c++) {
            const int col = col0 + c;
            float av[4];
#pragma unroll
            for (int r = 0; r < 4; r++) {
                const float2 p = acc[r][2 * i + (c >> 1)];
                av[r] = (c & 1) ? p.y : p.x;
            }
            float ad[4];
            if constexpr (MODE == 0) {
                const float b = (c == 0) ? bv.x : (c == 1) ? bv.y : (c == 2) ? bv.z : bv.w;
#pragma unroll
                for (int r = 0; r < 4; r++) ad[r] = b;
            } else {
#pragma unroll
                for (int r = 0; r < 4; r++) ad[r] = ctxp[nidx[r] * H1_ + col];
            }
            float4 o;
            o.x = fmaxf(av[0] + ad[0], 0.f);
            o.y = fmaxf(av[1] + ad[1], 0.f);
            o.z = fmaxf(av[2] + ad[2], 0.f);
            o.w = fmaxf(av[3] + ad[3], 0.f);
            *reinterpret_cast<float4*>(dst_t + (size_t)col * RS + row0) = o;
        }
    }
}

// ------------------------------ main kernel --------------------------------
__global__ void __launch_bounds__(NTHREADS, 1)
surface_kernel(
    const float* __restrict__ centers,       const float* __restrict__ enc_g,
    const float* __restrict__ enc_node,      const float* __restrict__ neighbors,
    const float* __restrict__ normals,       const float* __restrict__ neigh_normals,
    const float* __restrict__ areas,         const float* __restrict__ neigh_areas,
    const float* __restrict__ basis_W1,      const float* __restrict__ basis_b1,
    const float* __restrict__ basis_W2,      const float* __restrict__ basis_b2,
    const float* __restrict__ agg_W1,
    const float* __restrict__ agg_W2,        const float* __restrict__ agg_b2,
    const float* __restrict__ agg_W3,        const float* __restrict__ agg_b3,
    float* __restrict__ out, const int n_nodes)
{
    extern __shared__ float sm[];
    const int t    = threadIdx.x;
    const int base = blockIdx.x * NPC;

    float* svol = sm + OFF_SVOL;
    float* ctx  = sm + OFF_CTX;
    float* invd = sm + OFF_INVD;
    float* dsum = sm + OFF_DSUM;
    float* ctxp = sm + OFF_CTXP;
    float* arow = sm + OFF_AROW;
    float* w3s  = sm + OFF_W3;
    float* actA = sm + OFF_ACTA;   // transposed [k][row], stride RS
    float* actB = sm + OFF_ACTB;

    // ---- build vol rows (row = nl*7 + p) ----
    if (t < MM) {
        float f[8] = {0.f,0.f,0.f,0.f,0.f,0.f,0.f,0.f};
        const int nl = t / PP, p = t % PP;
        const int node = base + nl;
        if (t < ROWS_ && node < n_nodes) {
            if (p == 0) {
                f[0] = centers[node*3+0]; f[1] = centers[node*3+1]; f[2] = centers[node*3+2];
                f[3] = normals[node*3+0]; f[4] = normals[node*3+1]; f[5] = normals[node*3+2];
                f[6] = logf(areas[node]) * 0.1f;
            } else {
                const int j  = p - 1;
                const int nb = node * NK + j;
                f[0] = neighbors[nb*3+0] + 1e-6f;      f[1] = neighbors[nb*3+1] + 1e-6f;
                f[2] = neighbors[nb*3+2] + 1e-6f;
                f[3] = neigh_normals[nb*3+0] + 1e-6f;  f[4] = neigh_normals[nb*3+1] + 1e-6f;
                f[5] = neigh_normals[nb*3+2] + 1e-6f;
                f[6] = logf(neigh_areas[nb]) * 0.1f + 1e-6f;
            }
        }
#pragma unroll
        for (int q = 0; q < 8; q++) svol[t*8 + q] = f[q];
    }
    // ---- per-node context (enc_node ++ enc_g) ----
    for (int idx = t; idx < NPC * DCTX; idx += NTHREADS) {
        const int nl = idx / DCTX, fi = idx % DCTX;
        const int node = base + nl;
        float vl = 0.f;
        if (node < n_nodes)
            vl = (fi < 32) ? enc_node[node*32 + fi] : enc_g[node*128 + (fi - 32)];
        ctx[nl*DCTX + fi] = vl;
    }
    __syncthreads();
    // ---- inverse distances ----
    if (t < NPC * NK) {
        const int nl = t / NK, j = t % NK;
        float d2 = 0.f;
#pragma unroll
        for (int q = 0; q < 7; q++) {
            const float d = svol[(nl*7)*8 + q] - svol[(nl*7 + 1 + j)*8 + q];
            d2 += d * d;
        }
        invd[nl*8 + j] = 1.f / sqrtf(d2);
    }
    __syncthreads();
    if (t < NPC) {
        float s = 0.f;
#pragma unroll
        for (int j = 0; j < NK; j++) s += invd[t*8 + j];
        dsum[t] = s;
    }

    for (int v = 0; v < V_; v++) {
        // ---- L1: actA_t[col][row] = relu(vol @ basis_W1 + b1), K=7 ----
        {
            const int col = t;
            const float* W1 = basis_W1 + (size_t)v * 7 * H1_ + col;
            float w[7];
#pragma unroll
            for (int k = 0; k < 7; k++) w[k] = __ldg(W1 + k * H1_);
            const float b = __ldg(basis_b1 + v * H1_ + col);
#pragma unroll 2
            for (int r0 = 0; r0 < MM; r0 += 4) {
                float4 o;
                float* op = &o.x;
#pragma unroll
                for (int r = 0; r < 4; r++) {
                    float s = b;
#pragma unroll
                    for (int k = 0; k < 7; k++) s += svol[(r0 + r)*8 + k] * w[k];
                    op[r] = fmaxf(s, 0.f);
                }
                *reinterpret_cast<float4*>(actA + (size_t)col * RS + r0) = o;
            }
        }
        // ---- per-node ctx GEMM: ctxp[nl] = ctx[nl] @ agg_W1[256:416] + cst3 ----
        {
            const int col = t;
            float acc[NPC];
#pragma unroll
            for (int nl = 0; nl < NPC; nl++) acc[nl] = 0.f;
            const float* Wc = agg_W1 + ((size_t)v * 448 + 256) * H1_ + col;
#pragma unroll 4
            for (int k = 0; k < DCTX; k++) {
                const float wv = __ldg(Wc + (size_t)k * H1_);
#pragma unroll
                for (int nl = 0; nl < NPC; nl++) acc[nl] += ctx[nl*DCTX + k] * wv;
            }
            const float cst = g_cst3[v][col];
#pragma unroll
            for (int nl = 0; nl < NPC; nl++) ctxp[nl*H1_ + col] = acc[nl] + cst;
        }
        // ---- L2: actB = relu(actA @ basis_W2 + b2) ----
        gemm_layer<256, 0>(sm, actA, actB, basis_W2 + (size_t)v * H1_ * H1_, basis_b2 + v * H1_);
        // ---- L3: actA = relu(actB @ agg_W1[0:256] + ctxp[node]) ----
        gemm_layer<256, 1>(sm, actB, actA, agg_W1 + (size_t)v * 448 * H1_, nullptr);
        // ---- L4: actB = relu(actA @ agg_W2 + b4) ----
        gemm_layer<128, 0>(sm, actA, actB, agg_W2 + (size_t)v * H1_ * H2_, agg_b2 + v * H2_);
        // ---- L5: per-row scalar head (transposed layout: conflict-free) ----
        if (t < H2_) w3s[t] = __ldg(agg_W3 + v * H2_ + t);
        __syncthreads();
        if (t < MM) {
            const int row = t;
            float s = __ldg(agg_b3 + v);
#pragma unroll 8
            for (int k = 0; k < H2_; k++)
                s += actB[(size_t)k * RS + row] * w3s[k];
            arow[row] = s;
        }
        __syncthreads();
        // ---- inverse-distance aggregation + output ----
        if (t < NPC) {
            const int node = base + t;
            if (node < n_nodes) {
                const float c = arow[t*7];
                float s = 0.f;
#pragma unroll
                for (int j = 0; j < NK; j++) s += arow[t*7 + 1 + j] * invd[t*8 + j];
                out[node * V_ + v] = 0.5f * c + 0.5f * s / dsum[t];
            }
        }
        __syncthreads();
    }
}

// ------------------------------ launcher ------------------------------------
extern "C" void kernel_launch(void* const* d_in, const int* in_sizes, int n_in,
                              void* d_out, int out_size)
{
    const float* centers       = (const float*)d_in[0];
    const float* enc_g         = (const float*)d_in[1];
    const float* enc_node      = (const float*)d_in[2];
    const float* neighbors     = (const float*)d_in[3];
    const float* normals       = (const float*)d_in[4];
    const float* neigh_normals = (const float*)d_in[5];
    const float* areas         = (const float*)d_in[6];
    const float* neigh_areas   = (const float*)d_in[7];
    const float* gpv           = (const float*)d_in[8];
    const float* gpr           = (const float*)d_in[9];
    const float* param_W       = (const float*)d_in[10];
    const float* param_b       = (const float*)d_in[11];
    const float* basis_W1      = (const float*)d_in[12];
    const float* basis_b1      = (const float*)d_in[13];
    const float* basis_W2      = (const float*)d_in[14];
    const float* basis_b2      = (const float*)d_in[15];
    const float* agg_W1        = (const float*)d_in[16];
    const float* agg_b1        = (const float*)d_in[17];
    const float* agg_W2        = (const float*)d_in[18];
    const float* agg_b2        = (const float*)d_in[19];
    const float* agg_W3        = (const float*)d_in[20];
    const float* agg_b3        = (const float*)d_in[21];
    float* out = (float*)d_out;

    const int n_nodes = in_sizes[0] / 3;                 // 50000
    const int grid = (n_nodes + NPC - 1) / NPC;          // 5556

    cudaFuncSetAttribute(surface_kernel,
                         cudaFuncAttributeMaxDynamicSharedMemorySize, SMEM_BYTES);

    precompute_kernel<<<1, 256>>>(gpv, gpr, param_W, param_b, agg_W1, agg_b1);
    surface_kernel<<<grid, NTHREADS, SMEM_BYTES>>>(
        centers, enc_g, enc_node, neighbors, normals, neigh_normals,
        areas, neigh_areas,
        basis_W1, basis_b1, basis_W2, basis_b2,
        agg_W1, agg_W2, agg_b2, agg_W3, agg_b3,
        out, n_nodes);
}

// round 3
// speedup vs baseline: 1.1634x; 1.0539x over previous
#include <cuda_runtime.h>
#include <math.h>

// ---------------------------------------------------------------------------
// SolutionCalculatorSurface — fused per-node-tile MLP chain, round 2.
// Changes vs R1:
//  * thread mapping swapped (tx=t>>4) -> weight LDS broadcast (1 wavefront)
//  * activations stored transposed [k][row], padded stride 68 -> one LDS.128
//    per thread per k (2 wavefronts) instead of 4 scalar LDS
//  * weight tiles double-buffered via cp.async (latency hidden)
// ---------------------------------------------------------------------------

constexpr int V_   = 4;
constexpr int NK   = 6;
constexpr int PP   = 7;
constexpr int NPC  = 9;     // nodes per CTA
constexpr int ROWS_= 63;    // NPC * PP
constexpr int MM   = 64;    // padded rows
constexpr int NTHREADS = 256;
constexpr int H1_  = 256;
constexpr int H2_  = 128;
constexpr int DCTX = 160;   // enc_node(32) + enc_g(128)
constexpr int RS   = 68;    // padded row stride of transposed activations

// shared layout (float offsets)
constexpr int OFF_SVOL = 0;        // 512
constexpr int OFF_CTX  = 512;      // 1440
constexpr int OFF_INVD = 1952;     // 72
constexpr int OFF_DSUM = 2024;     // 24 (pad)
constexpr int OFF_CTXP = 2048;     // 2304
constexpr int OFF_AROW = 4352;     // 64
constexpr int OFF_W3   = 4416;     // 128
constexpr int OFF_ACTA = 4544;     // 256*68 = 17408
constexpr int OFF_ACTB = 21952;    // 17408
constexpr int OFF_WT   = 39360;    // 2 * 32*256 = 16384
constexpr int SMEM_FLOATS = 55744;
constexpr int SMEM_BYTES  = SMEM_FLOATS * 4;   // 222976 B

__device__ float g_cst3[V_][H1_];

// --------------------------- packed f32x2 FMA ------------------------------
__device__ __forceinline__ float2 ffma2(float2 d, float2 a, float2 b) {
    unsigned long long dd = *reinterpret_cast<unsigned long long*>(&d);
    unsigned long long aa = *reinterpret_cast<unsigned long long*>(&a);
    unsigned long long bb = *reinterpret_cast<unsigned long long*>(&b);
    asm("fma.rn.f32x2 %0, %1, %2, %0;" : "+l"(dd) : "l"(aa), "l"(bb));
    return *reinterpret_cast<float2*>(&dd);
}

__device__ __forceinline__ void cp_async16(float* smem_dst, const float4* gsrc) {
    unsigned saddr = (unsigned)__cvta_generic_to_shared(smem_dst);
    asm volatile("cp.async.cg.shared.global [%0], [%1], 16;\n"
                 :: "r"(saddr), "l"(gsrc));
}
__device__ __forceinline__ void cp_async_commit() {
    asm volatile("cp.async.commit_group;\n" ::);
}
__device__ __forceinline__ void cp_async_wait0() {
    asm volatile("cp.async.wait_group 0;\n" ::);
}

// ------------------------- precompute (global ctx) -------------------------
__global__ void precompute_kernel(
    const float* __restrict__ gpv, const float* __restrict__ gpr,
    const float* __restrict__ param_W, const float* __restrict__ param_b,
    const float* __restrict__ agg_W1, const float* __restrict__ agg_b1)
{
    __shared__ float pe[32];
    const int t = threadIdx.x;
    const float p0 = gpv[0] / gpr[0];
    const float p1 = gpv[1] / gpr[1];
    if (t < 32) {
        float s = param_b[t] + p0 * param_W[t] + p1 * param_W[32 + t];
        pe[t] = fmaxf(s, 0.f);
    }
    __syncthreads();
    for (int idx = t; idx < V_ * H1_; idx += blockDim.x) {
        const int v = idx >> 8, c = idx & 255;
        const float* W = agg_W1 + ((size_t)v * 448 + 416) * H1_ + c;
        float s = agg_b1[v * H1_ + c];
#pragma unroll
        for (int k = 0; k < 32; k++) s += pe[k] * W[(size_t)k * H1_];
        g_cst3[v][c] = s;
    }
}

// --------------------------- fused GEMM layer -------------------------------
// dst_t[col][row] = relu(src_t(.)[256][64] GEMM Wg[256][NCOLS] + bias|ctxp).
// src_t / dst_t are [k][row] with row stride RS. MODE 0: bias, MODE 1: ctxp.
template <int NCOLS, int MODE>
__device__ __forceinline__ void gemm_layer(
    float* sm, const float* __restrict__ src_t, float* __restrict__ dst_t,
    const float* __restrict__ Wg, const float* __restrict__ bias)
{
    constexpr int NI   = NCOLS / 64;          // float4 weight chunks (4 or 2)
    constexpr int TILE = 32 * NCOLS;          // floats per k-tile
    constexpr int NLD  = (TILE / 4) / NTHREADS;
    const int t    = threadIdx.x;
    const int tx   = t >> 4;                  // col group 0..15
    const int ty   = t & 15;                  // row group 0..15
    const int row0 = ty * 4;
    float* wt = sm + OFF_WT;
    const float* ctxp = sm + OFF_CTXP;

    float2 acc[4][2 * NI];
#pragma unroll
    for (int r = 0; r < 4; r++)
#pragma unroll
        for (int i = 0; i < 2 * NI; i++) acc[r][i] = make_float2(0.f, 0.f);

    // prefetch tile 0
    {
        const float4* g4 = reinterpret_cast<const float4*>(Wg);
#pragma unroll
        for (int i = 0; i < NLD; i++)
            cp_async16(wt + (t + i * NTHREADS) * 4, g4 + t + i * NTHREADS);
        cp_async_commit();
    }

#pragma unroll 1
    for (int kt = 0; kt < 8; kt++) {
        cp_async_wait0();
        __syncthreads();
        if (kt + 1 < 8) {
            const float4* g4 = reinterpret_cast<const float4*>(Wg + (size_t)(kt + 1) * TILE);
            float* wb = wt + ((kt + 1) & 1) * TILE;
#pragma unroll
            for (int i = 0; i < NLD; i++)
                cp_async16(wb + (t + i * NTHREADS) * 4, g4 + t + i * NTHREADS);
            cp_async_commit();
        }
        const float* wb = wt + (kt & 1) * TILE;
        const float* ap = src_t + (size_t)(kt * 32) * RS + row0;
#pragma unroll 4
        for (int k = 0; k < 32; k++) {
            const float4 av = *reinterpret_cast<const float4*>(ap + k * RS);
            float4 q[NI];
#pragma unroll
            for (int i = 0; i < NI; i++)
                q[i] = *reinterpret_cast<const float4*>(wb + k * NCOLS + tx * 4 + i * 64);
            const float ar[4] = {av.x, av.y, av.z, av.w};
#pragma unroll
            for (int r = 0; r < 4; r++) {
                const float2 aa = make_float2(ar[r], ar[r]);
#pragma unroll
                for (int i = 0; i < NI; i++) {
                    acc[r][2 * i + 0] = ffma2(acc[r][2 * i + 0], aa, make_float2(q[i].x, q[i].y));
                    acc[r][2 * i + 1] = ffma2(acc[r][2 * i + 1], aa, make_float2(q[i].z, q[i].w));
                }
            }
        }
    }

    // epilogue: bias/ctx add + relu, write transposed (per-col float4 of rows)
    int nidx[4];
#pragma unroll
    for (int r = 0; r < 4; r++) {
        int node = (row0 + r) / 7; if (node > 8) node = 8;
        nidx[r] = node;
    }
#pragma unroll
    for (int i = 0; i < NI; i++) {
        const int col0 = tx * 4 + i * 64;
        float4 bv;
        if constexpr (MODE == 0)
            bv = __ldg(reinterpret_cast<const float4*>(bias + col0));
#pragma unroll
        for (int c = 0; c < 4; c++) {
            const int col = col0 + c;
            float av[4];
#pragma unroll
            for (int r = 0; r < 4; r++) {
                const float2 p = acc[r][2 * i + (c >> 1)];
                av[r] = (c & 1) ? p.y : p.x;
            }
            float ad[4];
            if constexpr (MODE == 0) {
                const float b = (c == 0) ? bv.x : (c == 1) ? bv.y : (c == 2) ? bv.z : bv.w;
#pragma unroll
                for (int r = 0; r < 4; r++) ad[r] = b;
            } else {
#pragma unroll
                for (int r = 0; r < 4; r++) ad[r] = ctxp[nidx[r] * H1_ + col];
            }
            float4 o;
            o.x = fmaxf(av[0] + ad[0], 0.f);
            o.y = fmaxf(av[1] + ad[1], 0.f);
            o.z = fmaxf(av[2] + ad[2], 0.f);
            o.w = fmaxf(av[3] + ad[3], 0.f);
            *reinterpret_cast<float4*>(dst_t + (size_t)col * RS + row0) = o;
        }
    }
}

// ------------------------------ main kernel --------------------------------
__global__ void __launch_bounds__(NTHREADS, 1)
surface_kernel(
    const float* __restrict__ centers,       const float* __restrict__ enc_g,
    const float* __restrict__ enc_node,      const float* __restrict__ neighbors,
    const float* __restrict__ normals,       const float* __restrict__ neigh_normals,
    const float* __restrict__ areas,         const float* __restrict__ neigh_areas,
    const float* __restrict__ basis_W1,      const float* __restrict__ basis_b1,
    const float* __restrict__ basis_W2,      const float* __restrict__ basis_b2,
    const float* __restrict__ agg_W1,
    const float* __restrict__ agg_W2,        const float* __restrict__ agg_b2,
    const float* __restrict__ agg_W3,        const float* __restrict__ agg_b3,
    float* __restrict__ out, const int n_nodes)
{
    extern __shared__ float sm[];
    const int t    = threadIdx.x;
    const int base = blockIdx.x * NPC;

    float* svol = sm + OFF_SVOL;
    float* ctx  = sm + OFF_CTX;
    float* invd = sm + OFF_INVD;
    float* dsum = sm + OFF_DSUM;
    float* ctxp = sm + OFF_CTXP;
    float* arow = sm + OFF_AROW;
    float* w3s  = sm + OFF_W3;
    float* actA = sm + OFF_ACTA;   // transposed [k][row], stride RS
    float* actB = sm + OFF_ACTB;

    // ---- build vol rows (row = nl*7 + p) ----
    if (t < MM) {
        float f[8] = {0.f,0.f,0.f,0.f,0.f,0.f,0.f,0.f};
        const int nl = t / PP, p = t % PP;
        const int node = base + nl;
        if (t < ROWS_ && node < n_nodes) {
            if (p == 0) {
                f[0] = centers[node*3+0]; f[1] = centers[node*3+1]; f[2] = centers[node*3+2];
                f[3] = normals[node*3+0]; f[4] = normals[node*3+1]; f[5] = normals[node*3+2];
                f[6] = logf(areas[node]) * 0.1f;
            } else {
                const int j  = p - 1;
                const int nb = node * NK + j;
                f[0] = neighbors[nb*3+0] + 1e-6f;      f[1] = neighbors[nb*3+1] + 1e-6f;
                f[2] = neighbors[nb*3+2] + 1e-6f;
                f[3] = neigh_normals[nb*3+0] + 1e-6f;  f[4] = neigh_normals[nb*3+1] + 1e-6f;
                f[5] = neigh_normals[nb*3+2] + 1e-6f;
                f[6] = logf(neigh_areas[nb]) * 0.1f + 1e-6f;
            }
        }
#pragma unroll
        for (int q = 0; q < 8; q++) svol[t*8 + q] = f[q];
    }
    // ---- per-node context (enc_node ++ enc_g) ----
    for (int idx = t; idx < NPC * DCTX; idx += NTHREADS) {
        const int nl = idx / DCTX, fi = idx % DCTX;
        const int node = base + nl;
        float vl = 0.f;
        if (node < n_nodes)
            vl = (fi < 32) ? enc_node[node*32 + fi] : enc_g[node*128 + (fi - 32)];
        ctx[nl*DCTX + fi] = vl;
    }
    __syncthreads();
    // ---- inverse distances ----
    if (t < NPC * NK) {
        const int nl = t / NK, j = t % NK;
        float d2 = 0.f;
#pragma unroll
        for (int q = 0; q < 7; q++) {
            const float d = svol[(nl*7)*8 + q] - svol[(nl*7 + 1 + j)*8 + q];
            d2 += d * d;
        }
        invd[nl*8 + j] = 1.f / sqrtf(d2);
    }
    __syncthreads();
    if (t < NPC) {
        float s = 0.f;
#pragma unroll
        for (int j = 0; j < NK; j++) s += invd[t*8 + j];
        dsum[t] = s;
    }

    for (int v = 0; v < V_; v++) {
        // ---- L1: actA_t[col][row] = relu(vol @ basis_W1 + b1), K=7 ----
        {
            const int col = t;
            const float* W1 = basis_W1 + (size_t)v * 7 * H1_ + col;
            float w[7];
#pragma unroll
            for (int k = 0; k < 7; k++) w[k] = __ldg(W1 + k * H1_);
            const float b = __ldg(basis_b1 + v * H1_ + col);
#pragma unroll 2
            for (int r0 = 0; r0 < MM; r0 += 4) {
                float4 o;
                float* op = &o.x;
#pragma unroll
                for (int r = 0; r < 4; r++) {
                    float s = b;
#pragma unroll
                    for (int k = 0; k < 7; k++) s += svol[(r0 + r)*8 + k] * w[k];
                    op[r] = fmaxf(s, 0.f);
                }
                *reinterpret_cast<float4*>(actA + (size_t)col * RS + r0) = o;
            }
        }
        // ---- per-node ctx GEMM: ctxp[nl] = ctx[nl] @ agg_W1[256:416] + cst3 ----
        {
            const int col = t;
            float acc[NPC];
#pragma unroll
            for (int nl = 0; nl < NPC; nl++) acc[nl] = 0.f;
            const float* Wc = agg_W1 + ((size_t)v * 448 + 256) * H1_ + col;
#pragma unroll 4
            for (int k = 0; k < DCTX; k++) {
                const float wv = __ldg(Wc + (size_t)k * H1_);
#pragma unroll
                for (int nl = 0; nl < NPC; nl++) acc[nl] += ctx[nl*DCTX + k] * wv;
            }
            const float cst = g_cst3[v][col];
#pragma unroll
            for (int nl = 0; nl < NPC; nl++) ctxp[nl*H1_ + col] = acc[nl] + cst;
        }
        // ---- L2: actB = relu(actA @ basis_W2 + b2) ----
        gemm_layer<256, 0>(sm, actA, actB, basis_W2 + (size_t)v * H1_ * H1_, basis_b2 + v * H1_);
        // ---- L3: actA = relu(actB @ agg_W1[0:256] + ctxp[node]) ----
        gemm_layer<256, 1>(sm, actB, actA, agg_W1 + (size_t)v * 448 * H1_, nullptr);
        // ---- L4: actB = relu(actA @ agg_W2 + b4) ----
        gemm_layer<128, 0>(sm, actA, actB, agg_W2 + (size_t)v * H1_ * H2_, agg_b2 + v * H2_);
        // ---- L5: per-row scalar head (transposed layout: conflict-free) ----
        if (t < H2_) w3s[t] = __ldg(agg_W3 + v * H2_ + t);
        __syncthreads();
        if (t < MM) {
            const int row = t;
            float s = __ldg(agg_b3 + v);
#pragma unroll 8
            for (int k = 0; k < H2_; k++)
                s += actB[(size_t)k * RS + row] * w3s[k];
            arow[row] = s;
        }
        __syncthreads();
        // ---- inverse-distance aggregation + output ----
        if (t < NPC) {
            const int node = base + t;
            if (node < n_nodes) {
                const float c = arow[t*7];
                float s = 0.f;
#pragma unroll
                for (int j = 0; j < NK; j++) s += arow[t*7 + 1 + j] * invd[t*8 + j];
                out[node * V_ + v] = 0.5f * c + 0.5f * s / dsum[t];
            }
        }
        __syncthreads();
    }
}

// ------------------------------ launcher ------------------------------------
extern "C" void kernel_launch(void* const* d_in, const int* in_sizes, int n_in,
                              void* d_out, int out_size)
{
    const float* centers       = (const float*)d_in[0];
    const float* enc_g         = (const float*)d_in[1];
    const float* enc_node      = (const float*)d_in[2];
    const float* neighbors     = (const float*)d_in[3];
    const float* normals       = (const float*)d_in[4];
    const float* neigh_normals = (const float*)d_in[5];
    const float* areas         = (const float*)d_in[6];
    const float* neigh_areas   = (const float*)d_in[7];
    const float* gpv           = (const float*)d_in[8];
    const float* gpr           = (const float*)d_in[9];
    const float* param_W       = (const float*)d_in[10];
    const float* param_b       = (const float*)d_in[11];
    const float* basis_W1      = (const float*)d_in[12];
    const float* basis_b1      = (const float*)d_in[13];
    const float* basis_W2      = (const float*)d_in[14];
    const float* basis_b2      = (const float*)d_in[15];
    const float* agg_W1        = (const float*)d_in[16];
    const float* agg_b1        = (const float*)d_in[17];
    const float* agg_W2        = (const float*)d_in[18];
    const float* agg_b2        = (const float*)d_in[19];
    const float* agg_W3        = (const float*)d_in[20];
    const float* agg_b3        = (const float*)d_in[21];
    float* out = (float*)d_out;

    const int n_nodes = in_sizes[0] / 3;                 // 50000
    const int grid = (n_nodes + NPC - 1) / NPC;          // 5556

    cudaFuncSetAttribute(surface_kernel,
                         cudaFuncAttributeMaxDynamicSharedMemorySize, SMEM_BYTES);

    precompute_kernel<<<1, 256>>>(gpv, gpr, param_W, param_b, agg_W1, agg_b1);
    surface_kernel<<<grid, NTHREADS, SMEM_BYTES>>>(
        centers, enc_g, enc_node, neighbors, normals, neigh_normals,
        areas, neigh_areas,
        basis_W1, basis_b1, basis_W2, basis_b2,
        agg_W1, agg_W2, agg_b2, agg_W3, agg_b3,
        out, n_nodes);
}

// round 5
// speedup vs baseline: 2.2148x; 1.9036x over previous
#include <cuda_runtime.h>
#include <cuda_bf16.h>
#include <math.h>
#include <stdint.h>

constexpr int V_ = 4;
constexpr int NK = 6;
constexpr int PP = 7;
constexpr int NPC = 18;
constexpr int ROWS_ = 126;
constexpr int NT = 512;
constexpr int NNODES = 50000;

// weight blob: per v: L2 8 chunks x 32KB, L3 8 x 32KB, L4 8 x 16KB
constexpr int CB256 = 32768, CB128 = 16384;
constexpr int L3OFF = 8 * CB256, L4OFF = 16 * CB256;
constexpr int VSTRIDE = 16 * CB256 + 8 * CB128;   // 655360

__device__ uint8_t g_wB[(size_t)V_ * VSTRIDE];
__device__ float   g_cst3[V_][256];
__device__ float   g_ctxp[V_][NNODES][256];

// ---- smem byte offsets ----
constexpr int OFF_W    = 0;        // 65536 (2 x 32KB W double buffer)
constexpr int OFF_AHI  = 65536;    // 65536 (A hi frags: 8wm x 16fk x 32lane x 16B)
constexpr int OFF_ALO  = 131072;   // 65536
constexpr int OFF_CTXP = 196608;   // 18*260*4 = 18720
constexpr int OFF_SVOL = 215328;   // 128*8*4 = 4096
constexpr int OFF_W1S  = 219424;   // 7*256*4 = 7168
constexpr int OFF_B1S  = 226592;   // 1024
constexpr int OFF_B2S  = 227616;   // 1024
constexpr int OFF_B4S  = 228640;   // 512
constexpr int OFF_W3S  = 229152;   // 512
constexpr int OFF_ARP  = 229664;   // 1024
constexpr int OFF_ARW  = 230688;   // 512
constexpr int OFF_INVD = 231200;   // 576
constexpr int OFF_DSUM = 231776;   // 96
constexpr int SMEM_BYTES = 231872;

// ============================ PTX helpers ====================================
__device__ __forceinline__ uint32_t su32(const void* p) {
    return (uint32_t)__cvta_generic_to_shared(p);
}
__device__ __forceinline__ void cp16(uint8_t* s, const uint8_t* g) {
    uint32_t sa = su32(s);
    asm volatile("cp.async.cg.shared.global [%0], [%1], 16;" :: "r"(sa), "l"(g));
}
#define CP_COMMIT() asm volatile("cp.async.commit_group;" ::: "memory")
#define CP_WAIT1()  asm volatile("cp.async.wait_group 1;" ::: "memory")
#define CP_WAIT0()  asm volatile("cp.async.wait_group 0;" ::: "memory")

#define MMA_BF16(acc, a, b0, b1) asm volatile( \
    "mma.sync.aligned.m16n8k16.row.col.f32.bf16.bf16.f32 " \
    "{%0,%1,%2,%3}, {%4,%5,%6,%7}, {%8,%9}, {%0,%1,%2,%3};" \
    : "+f"((acc)[0]), "+f"((acc)[1]), "+f"((acc)[2]), "+f"((acc)[3]) \
    : "r"((a).x), "r"((a).y), "r"((a).z), "r"((a).w), "r"(b0), "r"(b1))

#define LDSM4(r0, r1, r2, r3, addr) asm volatile( \
    "ldmatrix.sync.aligned.m8n8.x4.shared.b16 {%0,%1,%2,%3}, [%4];" \
    : "=r"(r0), "=r"(r1), "=r"(r2), "=r"(r3) : "r"(addr))

__device__ __forceinline__ void relu_split(float x, float y, uint32_t& h, uint32_t& l) {
    x = fmaxf(x, 0.f); y = fmaxf(y, 0.f);
    __nv_bfloat162 hb = __float22bfloat162_rn(make_float2(x, y));
    float2 hf = __bfloat1622float2(hb);
    __nv_bfloat162 lb = __float22bfloat162_rn(make_float2(x - hf.x, y - hf.y));
    h = *reinterpret_cast<uint32_t*>(&hb);
    l = *reinterpret_cast<uint32_t*>(&lb);
}
__device__ __forceinline__ void ffma2s(float2& d, float a, float2 b) {
    unsigned long long dd = *reinterpret_cast<unsigned long long*>(&d);
    float2 av = make_float2(a, a);
    unsigned long long aa = *reinterpret_cast<unsigned long long*>(&av);
    unsigned long long bb = *reinterpret_cast<unsigned long long*>(&b);
    asm("fma.rn.f32x2 %0, %1, %2, %0;" : "+l"(dd) : "l"(aa), "l"(bb));
    d = *reinterpret_cast<float2*>(&dd);
}

// ===================== side kernel 1: cst3 ===================================
__global__ void cst3_kernel(const float* __restrict__ gpv, const float* __restrict__ gpr,
                            const float* __restrict__ pW, const float* __restrict__ pb,
                            const float* __restrict__ aW1, const float* __restrict__ ab1)
{
    __shared__ float pe[32];
    const int t = threadIdx.x;
    const float p0 = gpv[0] / gpr[0], p1 = gpv[1] / gpr[1];
    if (t < 32) pe[t] = fmaxf(pb[t] + p0 * pW[t] + p1 * pW[32 + t], 0.f);
    __syncthreads();
    for (int idx = t; idx < V_ * 256; idx += blockDim.x) {
        const int v = idx >> 8, c = idx & 255;
        const float* W = aW1 + ((size_t)v * 448 + 416) * 256 + c;
        float s = ab1[v * 256 + c];
#pragma unroll
        for (int k = 0; k < 32; k++) s += pe[k] * W[(size_t)k * 256];
        g_cst3[v][c] = s;
    }
}

// ===================== side kernel 2: ctxp GEMM ==============================
__global__ void __launch_bounds__(256)
ctxp_kernel(const float* __restrict__ enc_node, const float* __restrict__ enc_g,
            const float* __restrict__ aW1, const int n_nodes)
{
    __shared__ float ctxs[64 * 160];
    const int v = blockIdx.y;
    const int base = blockIdx.x * 64;
    const int t = threadIdx.x;
    for (int idx = t; idx < 64 * 160; idx += 256) {
        const int nl = idx / 160, fi = idx % 160;
        const int node = base + nl;
        float val = 0.f;
        if (node < n_nodes)
            val = (fi < 32) ? enc_node[node * 32 + fi] : enc_g[node * 128 + (fi - 32)];
        ctxs[idx] = val;
    }
    __syncthreads();
    const int tx = t & 127, tg = t >> 7;
    float2 acc[32];
#pragma unroll
    for (int i = 0; i < 32; i++) acc[i] = make_float2(0.f, 0.f);
    const float* W = aW1 + ((size_t)v * 448 + 256) * 256 + 2 * tx;
#pragma unroll 2
    for (int k = 0; k < 160; k++) {
        const float2 w0 = __ldg((const float2*)(W + (size_t)k * 256));
#pragma unroll
        for (int nl = 0; nl < 32; nl++)
            ffma2s(acc[nl], ctxs[(tg * 32 + nl) * 160 + k], w0);
    }
    const float2 cst = make_float2(g_cst3[v][2 * tx], g_cst3[v][2 * tx + 1]);
#pragma unroll
    for (int nl = 0; nl < 32; nl++) {
        const int node = base + tg * 32 + nl;
        if (node < n_nodes)
            *(float2*)&g_ctxp[v][node][2 * tx] =
                make_float2(acc[nl].x + cst.x, acc[nl].y + cst.y);
    }
}

// ===================== side kernel 3: weight convert =========================
// dest rows [n][64k] bf16, swizzled: byte = n*128 + ((2*kl) ^ ((n&7)<<4)).
// chunks 0-3: hi(k 0..255); chunks 4-7: lo(k 0..255).
__global__ void wconv_kernel(const float* __restrict__ bW2,
                             const float* __restrict__ aW1,
                             const float* __restrict__ aW2)
{
    const int total = V_ * 327680;
    for (int idx = blockIdx.x * blockDim.x + threadIdx.x; idx < total;
         idx += gridDim.x * blockDim.x) {
        const int v = idx / 327680;
        int e = idx % 327680;
        int loff, cbytes, c, n, kl;
        float w;
        if (e < 131072) {
            c = e >> 14; n = (e >> 6) & 255; kl = e & 63;
            w = bW2[((size_t)v * 256 + (c & 3) * 64 + kl) * 256 + n];
            loff = 0; cbytes = CB256;
        } else if (e < 262144) {
            e -= 131072;
            c = e >> 14; n = (e >> 6) & 255; kl = e & 63;
            w = aW1[((size_t)v * 448 + (c & 3) * 64 + kl) * 256 + n];
            loff = L3OFF; cbytes = CB256;
        } else {
            e -= 262144;
            c = e >> 13; n = (e >> 6) & 127; kl = e & 63;
            w = aW2[((size_t)v * 256 + (c & 3) * 64 + kl) * 128 + n];
            loff = L4OFF; cbytes = CB128;
        }
        __nv_bfloat16 hi = __float2bfloat16_rn(w);
        __nv_bfloat16 val = (c < 4) ? hi
                          : __float2bfloat16_rn(w - __bfloat162float(hi));
        uint8_t* p = g_wB + (size_t)v * VSTRIDE + loff + (size_t)c * cbytes
                   + n * 128 + (((uint32_t)(kl * 2)) ^ (((uint32_t)n & 7) << 4));
        *reinterpret_cast<__nv_bfloat16*>(p) = val;
    }
}

// ===================== streamed split-bf16 MMA layer ========================
// acc[NFRAG][4] += A(128x256 hi/lo frags in smem) @ W(streamed, hi then lo)
template <int NFRAG>
__device__ __forceinline__ void gemm_mma(
    uint8_t* sb, const uint8_t* wsrc, int t, int wm, int wn, float (*acc)[4])
{
    const int lane = t & 31;
    constexpr int CB = NFRAG * 2048;
    constexpr int NCP = CB / 16 / NT;   // 4 or 2
    uint8_t* w0 = sb + OFF_W;
    const uint4* AHI = (const uint4*)(sb + OFF_AHI);
    const uint4* ALO = (const uint4*)(sb + OFF_ALO);

#pragma unroll
    for (int i = 0; i < NCP; i++)
        cp16(w0 + (t + i * NT) * 16, wsrc + (size_t)(t + i * NT) * 16);
    CP_COMMIT();
#pragma unroll
    for (int i = 0; i < NCP; i++)
        cp16(w0 + 32768 + (t + i * NT) * 16, wsrc + CB + (size_t)(t + i * NT) * 16);
    CP_COMMIT();

    const uint32_t swzc = ((uint32_t)lane & 7) << 4;
    const int nbase = wn * (8 * NFRAG) + 8 * ((lane >> 4) & 1) + (lane & 7);
    const int kadd = ((lane >> 3) & 1) * 8;

#pragma unroll 1
    for (int c = 0; c < 8; c++) {
        if (c < 7) CP_WAIT1(); else CP_WAIT0();
        __syncthreads();
        const uint32_t wb = su32(w0 + (c & 1) * 32768);
        const bool hiB = (c < 4);
        const int fkb = (c & 3) * 4;
#pragma unroll
        for (int s = 0; s < 4; s++) {
            const int fk = fkb + s;
            const uint4 ah = AHI[(wm * 16 + fk) * 32 + lane];
            uint4 al = make_uint4(0, 0, 0, 0);
            if (hiB) al = ALO[(wm * 16 + fk) * 32 + lane];
            const int koff = s * 16 + kadd;
            const uint32_t ba = wb + (uint32_t)(nbase * 128)
                              + (((uint32_t)(koff * 2)) ^ swzc);
#pragma unroll
            for (int jj = 0; jj < NFRAG / 2; jj++) {
                uint32_t b0, b1, b2, b3;
                LDSM4(b0, b1, b2, b3, ba + jj * 2048);
                MMA_BF16(acc[2 * jj],     ah, b0, b1);
                MMA_BF16(acc[2 * jj + 1], ah, b2, b3);
                if (hiB) {
                    MMA_BF16(acc[2 * jj],     al, b0, b1);
                    MMA_BF16(acc[2 * jj + 1], al, b2, b3);
                }
            }
        }
        __syncthreads();
        if (c + 2 < 8) {
#pragma unroll
            for (int i = 0; i < NCP; i++)
                cp16(w0 + (c & 1) * 32768 + (t + i * NT) * 16,
                     wsrc + (size_t)(c + 2) * CB + (size_t)(t + i * NT) * 16);
            CP_COMMIT();
        }
    }
}

// ===================== epilogue: C frags -> A frags =========================
// MODE 0: add bias[col] (shared across rows); MODE 1: add ctxps[node][col].
template <int MODE>
__device__ __forceinline__ void epiA(
    uint8_t* sb, float (*acc)[4], const float* __restrict__ addv,
    int wm, int wn, int lane)
{
    uint4* AHI = (uint4*)(sb + OFF_AHI);
    uint4* ALO = (uint4*)(sb + OFF_ALO);
    const int quad = lane >> 2, q4 = lane & 3;
    const int r0 = 16 * wm + quad;
    int n0 = r0 / 7;       if (n0 > 17) n0 = 17;
    int n1 = (r0 + 8) / 7; if (n1 > 17) n1 = 17;
#pragma unroll
    for (int u = 0; u < 8; u++) {
        const int c0 = wn * 128 + 16 * u + 2 * q4;
        const int c2 = c0 + 8;
        float2 a00, a01, a10, a11;
        if constexpr (MODE == 0) {
            a00 = *(const float2*)(addv + c0);
            a01 = *(const float2*)(addv + c2);
            a10 = a00; a11 = a01;
        } else {
            a00 = *(const float2*)(addv + n0 * 260 + c0);
            a01 = *(const float2*)(addv + n0 * 260 + c2);
            a10 = *(const float2*)(addv + n1 * 260 + c0);
            a11 = *(const float2*)(addv + n1 * 260 + c2);
        }
        uint32_t h0, l0, h1, l1, h2, l2, h3, l3;
        relu_split(acc[2*u][0]   + a00.x, acc[2*u][1]   + a00.y, h0, l0);
        relu_split(acc[2*u][2]   + a10.x, acc[2*u][3]   + a10.y, h1, l1);
        relu_split(acc[2*u+1][0] + a01.x, acc[2*u+1][1] + a01.y, h2, l2);
        relu_split(acc[2*u+1][2] + a11.x, acc[2*u+1][3] + a11.y, h3, l3);
        const int fi = (wm * 16 + 8 * wn + u) * 32 + lane;
        AHI[fi] = make_uint4(h0, h1, h2, h3);
        ALO[fi] = make_uint4(l0, l1, l2, l3);
    }
}

// ============================ main kernel ====================================
__global__ void __launch_bounds__(NT, 1)
surface_kernel(
    const float* __restrict__ centers,  const float* __restrict__ neighbors,
    const float* __restrict__ normals,  const float* __restrict__ neigh_normals,
    const float* __restrict__ areas,    const float* __restrict__ neigh_areas,
    const float* __restrict__ basis_W1, const float* __restrict__ basis_b1,
    const float* __restrict__ basis_b2, const float* __restrict__ agg_b2,
    const float* __restrict__ agg_W3,   const float* __restrict__ agg_b3,
    float* __restrict__ out, const int n_nodes)
{
    extern __shared__ uint8_t sb[];
    const int t = threadIdx.x;
    const int wid = t >> 5, lane = t & 31;
    const int wm = wid & 7, wn = wid >> 3;
    const int quad = lane >> 2, q4 = lane & 3;
    const int base = blockIdx.x * NPC;

    float* ctxps = (float*)(sb + OFF_CTXP);
    float* svol  = (float*)(sb + OFF_SVOL);
    float* W1s   = (float*)(sb + OFF_W1S);
    float* b1s   = (float*)(sb + OFF_B1S);
    float* b2s   = (float*)(sb + OFF_B2S);
    float* b4s   = (float*)(sb + OFF_B4S);
    float* w3s   = (float*)(sb + OFF_W3S);
    float* arowp = (float*)(sb + OFF_ARP);
    float* arow  = (float*)(sb + OFF_ARW);
    float* invd  = (float*)(sb + OFF_INVD);
    float* dsum  = (float*)(sb + OFF_DSUM);

    // ---- build vol rows ----
    if (t < 128) {
        float f[8] = {0.f,0.f,0.f,0.f,0.f,0.f,0.f,0.f};
        const int nl = t / PP, p = t % PP;
        const int node = base + nl;
        if (t < ROWS_ && node < n_nodes) {
            if (p == 0) {
                f[0]=centers[node*3+0]; f[1]=centers[node*3+1]; f[2]=centers[node*3+2];
                f[3]=normals[node*3+0]; f[4]=normals[node*3+1]; f[5]=normals[node*3+2];
                f[6]=logf(areas[node]) * 0.1f;
            } else {
                const int nb = node * NK + (p - 1);
                f[0]=neighbors[nb*3+0]+1e-6f; f[1]=neighbors[nb*3+1]+1e-6f;
                f[2]=neighbors[nb*3+2]+1e-6f;
                f[3]=neigh_normals[nb*3+0]+1e-6f; f[4]=neigh_normals[nb*3+1]+1e-6f;
                f[5]=neigh_normals[nb*3+2]+1e-6f;
                f[6]=logf(neigh_areas[nb]) * 0.1f + 1e-6f;
            }
        }
#pragma unroll
        for (int q = 0; q < 8; q++) svol[t * 8 + q] = f[q];
    }
    __syncthreads();
    if (t < NPC * NK) {
        const int nl = t / NK, j = t % NK;
        float d2 = 0.f;
#pragma unroll
        for (int q = 0; q < 7; q++) {
            const float d = svol[(nl*7)*8 + q] - svol[(nl*7 + 1 + j)*8 + q];
            d2 += d * d;
        }
        invd[nl * 8 + j] = 1.f / sqrtf(d2);
    }
    __syncthreads();
    if (t < NPC) {
        float s = 0.f;
#pragma unroll
        for (int j = 0; j < NK; j++) s += invd[t * 8 + j];
        dsum[t] = s;
    }

    const int r0 = 16 * wm + quad;
    float sv0[7], sv1[7];
#pragma unroll
    for (int q = 0; q < 7; q++) {
        sv0[q] = svol[r0 * 8 + q];
        sv1[q] = svol[(r0 + 8) * 8 + q];
    }

#pragma unroll 1
    for (int v = 0; v < V_; v++) {
        // per-v constants
        for (int i = t; i < 1792; i += NT) W1s[i] = __ldg(basis_W1 + (size_t)v * 1792 + i);
        if (t < 256) { b1s[t] = __ldg(basis_b1 + v * 256 + t);
                       b2s[t] = __ldg(basis_b2 + v * 256 + t); }
        else if (t < 384) { b4s[t-256] = __ldg(agg_b2 + v * 128 + (t-256)); }
        else { w3s[t-384] = __ldg(agg_W3 + v * 128 + (t-384)); }
        for (int i = t; i < NPC * 256; i += NT) {
            const int nl = i >> 8, c = i & 255;
            const int node = base + nl;
            ctxps[nl * 260 + c] = (node < n_nodes) ? g_ctxp[v][node][c] : 0.f;
        }
        __syncthreads();

        // ---- L1: produce A frags directly ----
        {
            uint4* AHI = (uint4*)(sb + OFF_AHI);
            uint4* ALO = (uint4*)(sb + OFF_ALO);
#pragma unroll
            for (int u = 0; u < 8; u++) {
                const int c0 = wn * 128 + 16 * u + 2 * q4;
                const int c2 = c0 + 8;
                float2 a00 = *(const float2*)(b1s + c0);
                float2 a01 = *(const float2*)(b1s + c2);
                float2 a10 = a00, a11 = a01;
#pragma unroll
                for (int q = 0; q < 7; q++) {
                    const float2 w0 = *(const float2*)(W1s + q * 256 + c0);
                    const float2 w2 = *(const float2*)(W1s + q * 256 + c2);
                    ffma2s(a00, sv0[q], w0); ffma2s(a01, sv0[q], w2);
                    ffma2s(a10, sv1[q], w0); ffma2s(a11, sv1[q], w2);
                }
                uint32_t h0, l0, h1, l1, h2, l2, h3, l3;
                relu_split(a00.x, a00.y, h0, l0);
                relu_split(a10.x, a10.y, h1, l1);
                relu_split(a01.x, a01.y, h2, l2);
                relu_split(a11.x, a11.y, h3, l3);
                const int fi = (wm * 16 + 8 * wn + u) * 32 + lane;
                AHI[fi] = make_uint4(h0, h1, h2, h3);
                ALO[fi] = make_uint4(l0, l1, l2, l3);
            }
        }

        const uint8_t* wv = g_wB + (size_t)v * VSTRIDE;
        // ---- L2 ----
        {
            float acc[16][4];
#pragma unroll
            for (int i = 0; i < 16; i++)
#pragma unroll
                for (int j = 0; j < 4; j++) acc[i][j] = 0.f;
            gemm_mma<16>(sb, wv, t, wm, wn, acc);
            epiA<0>(sb, acc, b2s, wm, wn, lane);
        }
        __syncthreads();
        // ---- L3 ----
        {
            float acc[16][4];
#pragma unroll
            for (int i = 0; i < 16; i++)
#pragma unroll
                for (int j = 0; j < 4; j++) acc[i][j] = 0.f;
            gemm_mma<16>(sb, wv + L3OFF, t, wm, wn, acc);
            epiA<1>(sb, acc, ctxps, wm, wn, lane);
        }
        __syncthreads();
        // ---- L4 + L5 ----
        {
            float acc[8][4];
#pragma unroll
            for (int i = 0; i < 8; i++)
#pragma unroll
                for (int j = 0; j < 4; j++) acc[i][j] = 0.f;
            gemm_mma<8>(sb, wv + L4OFF, t, wm, wn, acc);
            float s0 = 0.f, s1 = 0.f;
#pragma unroll
            for (int j = 0; j < 8; j++) {
                const int c0 = wn * 64 + 8 * j + 2 * q4;
                const float w30 = w3s[c0], w31 = w3s[c0 + 1];
                const float bb0 = b4s[c0], bb1 = b4s[c0 + 1];
                s0 += fmaxf(acc[j][0] + bb0, 0.f) * w30 + fmaxf(acc[j][1] + bb1, 0.f) * w31;
                s1 += fmaxf(acc[j][2] + bb0, 0.f) * w30 + fmaxf(acc[j][3] + bb1, 0.f) * w31;
            }
            s0 += __shfl_xor_sync(0xffffffffu, s0, 1);
            s0 += __shfl_xor_sync(0xffffffffu, s0, 2);
            s1 += __shfl_xor_sync(0xffffffffu, s1, 1);
            s1 += __shfl_xor_sync(0xffffffffu, s1, 2);
            if (q4 == 0) {
                arowp[wn * 128 + r0] = s0;
                arowp[wn * 128 + r0 + 8] = s1;
            }
        }
        __syncthreads();
        if (t < 128) arow[t] = arowp[t] + arowp[128 + t] + __ldg(agg_b3 + v);
        __syncthreads();
        if (t < NPC) {
            const int node = base + t;
            if (node < n_nodes) {
                const float c = arow[t * 7];
                float s = 0.f;
#pragma unroll
                for (int j = 0; j < NK; j++) s += arow[t * 7 + 1 + j] * invd[t * 8 + j];
                out[node * V_ + v] = 0.5f * c + 0.5f * s / dsum[t];
            }
        }
        __syncthreads();
    }
}

// ============================ launcher =======================================
extern "C" void kernel_launch(void* const* d_in, const int* in_sizes, int n_in,
                              void* d_out, int out_size)
{
    const float* centers       = (const float*)d_in[0];
    const float* enc_g         = (const float*)d_in[1];
    const float* enc_node      = (const float*)d_in[2];
    const float* neighbors     = (const float*)d_in[3];
    const float* normals       = (const float*)d_in[4];
    const float* neigh_normals = (const float*)d_in[5];
    const float* areas         = (const float*)d_in[6];
    const float* neigh_areas   = (const float*)d_in[7];
    const float* gpv           = (const float*)d_in[8];
    const float* gpr           = (const float*)d_in[9];
    const float* param_W       = (const float*)d_in[10];
    const float* param_b       = (const float*)d_in[11];
    const float* basis_W1      = (const float*)d_in[12];
    const float* basis_b1      = (const float*)d_in[13];
    const float* basis_W2      = (const float*)d_in[14];
    const float* basis_b2      = (const float*)d_in[15];
    const float* agg_W1        = (const float*)d_in[16];
    const float* agg_b1        = (const float*)d_in[17];
    const float* agg_W2        = (const float*)d_in[18];
    const float* agg_b2        = (const float*)d_in[19];
    const float* agg_W3        = (const float*)d_in[20];
    const float* agg_b3        = (const float*)d_in[21];
    float* out = (float*)d_out;

    const int n_nodes = in_sizes[0] / 3;
    const int grid = (n_nodes + NPC - 1) / NPC;

    cudaFuncSetAttribute(surface_kernel,
                         cudaFuncAttributeMaxDynamicSharedMemorySize, SMEM_BYTES);

    cst3_kernel<<<1, 256>>>(gpv, gpr, param_W, param_b, agg_W1, agg_b1);
    dim3 cg((n_nodes + 63) / 64, V_);
    ctxp_kernel<<<cg, 256>>>(enc_node, enc_g, agg_W1, n_nodes);
    wconv_kernel<<<2560, 512>>>(basis_W2, agg_W1, agg_W2);
    surface_kernel<<<grid, NT, SMEM_BYTES>>>(
        centers, neighbors, normals, neigh_normals, areas, neigh_areas,
        basis_W1, basis_b1, basis_b2, agg_b2, agg_W3, agg_b3, out, n_nodes);
}

// round 6
// speedup vs baseline: 2.3442x; 1.0584x over previous
#include <cuda_runtime.h>
#include <cuda_bf16.h>
#include <math.h>
#include <stdint.h>

constexpr int V_ = 4;
constexpr int NK = 6;
constexpr int PP = 7;
constexpr int NPC = 18;
constexpr int ROWS_ = 126;
constexpr int NT = 512;

// weight blob per v: L2 8x32KB | L3 8x32KB | L4 8x16KB | CTX 6x32KB
constexpr int CB256 = 32768, CB128 = 16384;
constexpr int L3OFF  = 8 * CB256;
constexpr int L4OFF  = 16 * CB256;
constexpr int CTXOFF = 16 * CB256 + 8 * CB128;           // 655360
constexpr int VSTRIDE = CTXOFF + 6 * CB256;               // 851968

__device__ uint8_t g_wB[(size_t)V_ * VSTRIDE];
__device__ float   g_cst3[V_][256];

// ---- smem byte offsets ----
constexpr int OFF_W    = 0;        // 65536 (2 x 32KB W double buffer)
constexpr int OFF_AHI  = 65536;    // 65536 (A hi frags: 128 slots x 512B)
constexpr int OFF_ALO  = 131072;   // 65536
constexpr int OFF_CTXP = 196608;   // 18*260*4 = 18720
constexpr int OFF_SVOL = 215328;   // 4096
constexpr int OFF_W1S  = 219424;   // 7168
constexpr int OFF_B1S  = 226592;   // 1024
constexpr int OFF_B2S  = 227616;   // 1024
constexpr int OFF_B4S  = 228640;   // 512
constexpr int OFF_W3S  = 229152;   // 512
constexpr int OFF_ARP  = 229664;   // 1024
constexpr int OFF_ARW  = 230688;   // 512
constexpr int OFF_INVD = 231200;   // 576
constexpr int OFF_DSUM = 231776;   // 96
constexpr int SMEM_BYTES = 231872;

// ============================ PTX helpers ====================================
__device__ __forceinline__ uint32_t su32(const void* p) {
    return (uint32_t)__cvta_generic_to_shared(p);
}
__device__ __forceinline__ void cp16(uint8_t* s, const uint8_t* g) {
    uint32_t sa = su32(s);
    asm volatile("cp.async.cg.shared.global [%0], [%1], 16;" :: "r"(sa), "l"(g));
}
#define CP_COMMIT() asm volatile("cp.async.commit_group;" ::: "memory")
#define CP_WAIT1()  asm volatile("cp.async.wait_group 1;" ::: "memory")
#define CP_WAIT0()  asm volatile("cp.async.wait_group 0;" ::: "memory")

#define MMA_BF16(acc, a, b0, b1) asm volatile( \
    "mma.sync.aligned.m16n8k16.row.col.f32.bf16.bf16.f32 " \
    "{%0,%1,%2,%3}, {%4,%5,%6,%7}, {%8,%9}, {%0,%1,%2,%3};" \
    : "+f"((acc)[0]), "+f"((acc)[1]), "+f"((acc)[2]), "+f"((acc)[3]) \
    : "r"((a).x), "r"((a).y), "r"((a).z), "r"((a).w), "r"(b0), "r"(b1))

#define LDSM4(r0, r1, r2, r3, addr) asm volatile( \
    "ldmatrix.sync.aligned.m8n8.x4.shared.b16 {%0,%1,%2,%3}, [%4];" \
    : "=r"(r0), "=r"(r1), "=r"(r2), "=r"(r3) : "r"(addr))

__device__ __forceinline__ void relu_split(float x, float y, uint32_t& h, uint32_t& l) {
    x = fmaxf(x, 0.f); y = fmaxf(y, 0.f);
    __nv_bfloat162 hb = __float22bfloat162_rn(make_float2(x, y));
    float2 hf = __bfloat1622float2(hb);
    __nv_bfloat162 lb = __float22bfloat162_rn(make_float2(x - hf.x, y - hf.y));
    h = *reinterpret_cast<uint32_t*>(&hb);
    l = *reinterpret_cast<uint32_t*>(&lb);
}
__device__ __forceinline__ void plain_split(float x, float y, uint32_t& h, uint32_t& l) {
    __nv_bfloat162 hb = __float22bfloat162_rn(make_float2(x, y));
    float2 hf = __bfloat1622float2(hb);
    __nv_bfloat162 lb = __float22bfloat162_rn(make_float2(x - hf.x, y - hf.y));
    h = *reinterpret_cast<uint32_t*>(&hb);
    l = *reinterpret_cast<uint32_t*>(&lb);
}
__device__ __forceinline__ void ffma2s(float2& d, float a, float2 b) {
    unsigned long long dd = *reinterpret_cast<unsigned long long*>(&d);
    float2 av = make_float2(a, a);
    unsigned long long aa = *reinterpret_cast<unsigned long long*>(&av);
    unsigned long long bb = *reinterpret_cast<unsigned long long*>(&b);
    asm("fma.rn.f32x2 %0, %1, %2, %0;" : "+l"(dd) : "l"(aa), "l"(bb));
    d = *reinterpret_cast<float2*>(&dd);
}

// ===================== side kernel 1: cst3 ===================================
__global__ void cst3_kernel(const float* __restrict__ gpv, const float* __restrict__ gpr,
                            const float* __restrict__ pW, const float* __restrict__ pb,
                            const float* __restrict__ aW1, const float* __restrict__ ab1)
{
    __shared__ float pe[32];
    const int t = threadIdx.x;
    const float p0 = gpv[0] / gpr[0], p1 = gpv[1] / gpr[1];
    if (t < 32) pe[t] = fmaxf(pb[t] + p0 * pW[t] + p1 * pW[32 + t], 0.f);
    __syncthreads();
    for (int idx = t; idx < V_ * 256; idx += blockDim.x) {
        const int v = idx >> 8, c = idx & 255;
        const float* W = aW1 + ((size_t)v * 448 + 416) * 256 + c;
        float s = ab1[v * 256 + c];
#pragma unroll
        for (int k = 0; k < 32; k++) s += pe[k] * W[(size_t)k * 256];
        g_cst3[v][c] = s;
    }
}

// ===================== side kernel 2: weight convert =========================
// all chunks: [n][64k] bf16 rows of 128B, swizzle byte = n*128 + ((2kl)^((n&7)<<4))
__global__ void wconv_kernel(const float* __restrict__ bW2,
                             const float* __restrict__ aW1,
                             const float* __restrict__ aW2)
{
    constexpr int PERV = 131072 + 131072 + 65536 + 98304;   // 425984
    const int total = V_ * PERV;
    for (int idx = blockIdx.x * blockDim.x + threadIdx.x; idx < total;
         idx += gridDim.x * blockDim.x) {
        const int v = idx / PERV;
        int e = idx % PERV;
        int loff, cbytes, c, n, kl;
        bool hiC;
        float w;
        if (e < 131072) {
            c = e >> 14; n = (e >> 6) & 255; kl = e & 63;
            w = bW2[((size_t)v * 256 + (c & 3) * 64 + kl) * 256 + n];
            loff = 0; cbytes = CB256; hiC = (c < 4);
        } else if (e < 262144) {
            e -= 131072;
            c = e >> 14; n = (e >> 6) & 255; kl = e & 63;
            w = aW1[((size_t)v * 448 + (c & 3) * 64 + kl) * 256 + n];
            loff = L3OFF; cbytes = CB256; hiC = (c < 4);
        } else if (e < 327680) {
            e -= 262144;
            c = e >> 13; n = (e >> 6) & 127; kl = e & 63;
            w = aW2[((size_t)v * 256 + (c & 3) * 64 + kl) * 128 + n];
            loff = L4OFF; cbytes = CB128; hiC = (c < 4);
        } else {
            e -= 327680;
            c = e >> 14; n = (e >> 6) & 255; kl = e & 63;
            const int k = (c % 3) * 64 + kl;
            w = (k < 160) ? aW1[((size_t)v * 448 + 256 + k) * 256 + n] : 0.f;
            loff = CTXOFF; cbytes = CB256; hiC = (c < 3);
        }
        __nv_bfloat16 hi = __float2bfloat16_rn(w);
        __nv_bfloat16 val = hiC ? hi : __float2bfloat16_rn(w - __bfloat162float(hi));
        uint8_t* p = g_wB + (size_t)v * VSTRIDE + loff + (size_t)c * cbytes
                   + n * 128 + (((uint32_t)(kl * 2)) ^ (((uint32_t)n & 7) << 4));
        *reinterpret_cast<__nv_bfloat16*>(p) = val;
    }
}

// ===================== prefetch + mainloop ===================================
template <int CBT>
__device__ __forceinline__ void prefetch2(uint8_t* sb, const uint8_t* wsrc, int t) {
    constexpr int NCP = CBT / 16 / NT;
    uint8_t* w0 = sb + OFF_W;
#pragma unroll
    for (int i = 0; i < NCP; i++)
        cp16(w0 + (t + i * NT) * 16, wsrc + (size_t)(t + i * NT) * 16);
    CP_COMMIT();
#pragma unroll
    for (int i = 0; i < NCP; i++)
        cp16(w0 + 32768 + (t + i * NT) * 16, wsrc + CBT + (size_t)(t + i * NT) * 16);
    CP_COMMIT();
}

// requires: prefetch2<CBT>(wsrc) already issued. 3-pass split-bf16 MMA mainloop.
template <int NCHUNK, int NFRAG, int CBT>
__device__ __forceinline__ void mma_loop(
    uint8_t* sb, const uint8_t* wsrc, int t, int aslot0, int nbase, float (*acc)[4])
{
    const int lane = t & 31;
    uint8_t* w0 = sb + OFF_W;
    const uint4* AHI = (const uint4*)(sb + OFF_AHI);
    const uint4* ALO = (const uint4*)(sb + OFF_ALO);
    const uint32_t swzc = ((uint32_t)lane & 7) << 4;
    const int kadd = ((lane >> 3) & 1) * 8;
    constexpr int NCP = CBT / 16 / NT;
#pragma unroll 1
    for (int c = 0; c < NCHUNK; c++) {
        if (c < NCHUNK - 1) CP_WAIT1(); else CP_WAIT0();
        __syncthreads();
        const uint32_t wb = su32(w0 + (c & 1) * 32768);
        const bool hiB = (c < NCHUNK / 2);
        const int fkb = (c % (NCHUNK / 2)) * 4;
#pragma unroll
        for (int s = 0; s < 4; s++) {
            const int fk = fkb + s;
            const uint4 ah = AHI[(aslot0 + fk) * 32 + lane];
            uint4 al = make_uint4(0, 0, 0, 0);
            if (hiB) al = ALO[(aslot0 + fk) * 32 + lane];
            const int koff = s * 16 + kadd;
            const uint32_t ba = wb + (uint32_t)(nbase * 128)
                              + (((uint32_t)(koff * 2)) ^ swzc);
#pragma unroll
            for (int jj = 0; jj < NFRAG / 2; jj++) {
                uint32_t b0, b1, b2, b3;
                LDSM4(b0, b1, b2, b3, ba + jj * 2048);
                MMA_BF16(acc[2 * jj],     ah, b0, b1);
                MMA_BF16(acc[2 * jj + 1], ah, b2, b3);
                if (hiB) {
                    MMA_BF16(acc[2 * jj],     al, b0, b1);
                    MMA_BF16(acc[2 * jj + 1], al, b2, b3);
                }
            }
        }
        __syncthreads();
        if (c + 2 < NCHUNK) {
#pragma unroll
            for (int i = 0; i < NCP; i++)
                cp16(w0 + (c & 1) * 32768 + (t + i * NT) * 16,
                     wsrc + (size_t)(c + 2) * CBT + (size_t)(t + i * NT) * 16);
            CP_COMMIT();
        }
    }
}

// ===================== epilogue: C frags -> A frags =========================
template <int MODE>
__device__ __forceinline__ void epiA(
    uint8_t* sb, float (*acc)[4], const float* __restrict__ addv,
    int wm, int wn, int lane)
{
    uint4* AHI = (uint4*)(sb + OFF_AHI);
    uint4* ALO = (uint4*)(sb + OFF_ALO);
    const int quad = lane >> 2, q4 = lane & 3;
    const int r0 = 16 * wm + quad;
    int n0 = r0 / 7;       if (n0 > 17) n0 = 17;
    int n1 = (r0 + 8) / 7; if (n1 > 17) n1 = 17;
#pragma unroll
    for (int u = 0; u < 8; u++) {
        const int c0 = wn * 128 + 16 * u + 2 * q4;
        const int c2 = c0 + 8;
        float2 a00, a01, a10, a11;
        if constexpr (MODE == 0) {
            a00 = *(const float2*)(addv + c0);
            a01 = *(const float2*)(addv + c2);
            a10 = a00; a11 = a01;
        } else {
            a00 = *(const float2*)(addv + n0 * 260 + c0);
            a01 = *(const float2*)(addv + n0 * 260 + c2);
            a10 = *(const float2*)(addv + n1 * 260 + c0);
            a11 = *(const float2*)(addv + n1 * 260 + c2);
        }
        uint32_t h0, l0, h1, l1, h2, l2, h3, l3;
        relu_split(acc[2*u][0]   + a00.x, acc[2*u][1]   + a00.y, h0, l0);
        relu_split(acc[2*u][2]   + a10.x, acc[2*u][3]   + a10.y, h1, l1);
        relu_split(acc[2*u+1][0] + a01.x, acc[2*u+1][1] + a01.y, h2, l2);
        relu_split(acc[2*u+1][2] + a11.x, acc[2*u+1][3] + a11.y, h3, l3);
        const int fi = (wm * 16 + 8 * wn + u) * 32 + lane;
        AHI[fi] = make_uint4(h0, h1, h2, h3);
        ALO[fi] = make_uint4(l0, l1, l2, l3);
    }
}

// ============================ main kernel ====================================
__global__ void __launch_bounds__(NT, 1)
surface_kernel(
    const float* __restrict__ centers,  const float* __restrict__ enc_g,
    const float* __restrict__ enc_node, const float* __restrict__ neighbors,
    const float* __restrict__ normals,  const float* __restrict__ neigh_normals,
    const float* __restrict__ areas,    const float* __restrict__ neigh_areas,
    const float* __restrict__ basis_W1, const float* __restrict__ basis_b1,
    const float* __restrict__ basis_b2, const float* __restrict__ agg_b2,
    const float* __restrict__ agg_W3,   const float* __restrict__ agg_b3,
    float* __restrict__ out, const int n_nodes)
{
    extern __shared__ uint8_t sb[];
    const int t = threadIdx.x;
    const int wid = t >> 5, lane = t & 31;
    const int wm = wid & 7, wn = wid >> 3;
    const int quad = lane >> 2, q4 = lane & 3;
    const int base = blockIdx.x * NPC;

    float* ctxps = (float*)(sb + OFF_CTXP);
    float* svol  = (float*)(sb + OFF_SVOL);
    float* W1s   = (float*)(sb + OFF_W1S);
    float* b1s   = (float*)(sb + OFF_B1S);
    float* b2s   = (float*)(sb + OFF_B2S);
    float* b4s   = (float*)(sb + OFF_B4S);
    float* w3s   = (float*)(sb + OFF_W3S);
    float* arowp = (float*)(sb + OFF_ARP);
    float* arow  = (float*)(sb + OFF_ARW);
    float* invd  = (float*)(sb + OFF_INVD);
    float* dsum  = (float*)(sb + OFF_DSUM);

    // prefetch v=0 ctx weight chunks before anything else
    prefetch2<CB256>(sb, g_wB + CTXOFF, t);

    // ---- build vol rows ----
    if (t < 128) {
        float f[8] = {0.f,0.f,0.f,0.f,0.f,0.f,0.f,0.f};
        const int nl = t / PP, p = t % PP;
        const int node = base + nl;
        if (t < ROWS_ && node < n_nodes) {
            if (p == 0) {
                f[0]=centers[node*3+0]; f[1]=centers[node*3+1]; f[2]=centers[node*3+2];
                f[3]=normals[node*3+0]; f[4]=normals[node*3+1]; f[5]=normals[node*3+2];
                f[6]=logf(areas[node]) * 0.1f;
            } else {
                const int nb = node * NK + (p - 1);
                f[0]=neighbors[nb*3+0]+1e-6f; f[1]=neighbors[nb*3+1]+1e-6f;
                f[2]=neighbors[nb*3+2]+1e-6f;
                f[3]=neigh_normals[nb*3+0]+1e-6f; f[4]=neigh_normals[nb*3+1]+1e-6f;
                f[5]=neigh_normals[nb*3+2]+1e-6f;
                f[6]=logf(neigh_areas[nb]) * 0.1f + 1e-6f;
            }
        }
#pragma unroll
        for (int q = 0; q < 8; q++) svol[t * 8 + q] = f[q];
    }
    __syncthreads();
    if (t < NPC * NK) {
        const int nl = t / NK, j = t % NK;
        float d2 = 0.f;
#pragma unroll
        for (int q = 0; q < 7; q++) {
            const float d = svol[(nl*7)*8 + q] - svol[(nl*7 + 1 + j)*8 + q];
            d2 += d * d;
        }
        invd[nl * 8 + j] = 1.f / sqrtf(d2);
    }
    __syncthreads();
    if (t < NPC) {
        float s = 0.f;
#pragma unroll
        for (int j = 0; j < NK; j++) s += invd[t * 8 + j];
        dsum[t] = s;
    }

    const int r0m = 16 * wm + quad;
    float sv0[7], sv1[7];
#pragma unroll
    for (int q = 0; q < 7; q++) {
        sv0[q] = svol[r0m * 8 + q];
        sv1[q] = svol[(r0m + 8) * 8 + q];
    }

#pragma unroll 1
    for (int v = 0; v < V_; v++) {
        const uint8_t* wv = g_wB + (size_t)v * VSTRIDE;
        // per-v constants (overlaps in-flight ctx weight copies)
        for (int i = t; i < 1792; i += NT) W1s[i] = __ldg(basis_W1 + (size_t)v * 1792 + i);
        if (t < 256) { b1s[t] = __ldg(basis_b1 + v * 256 + t);
                       b2s[t] = __ldg(basis_b2 + v * 256 + t); }
        else if (t < 384) { b4s[t-256] = __ldg(agg_b2 + v * 128 + (t-256)); }
        else { w3s[t-384] = __ldg(agg_W3 + v * 128 + (t-384)); }

        // ---- build ctx A frags (M=32 rows of node context, K padded to 192) ----
        {
            uint4* AHI = (uint4*)(sb + OFF_AHI);
            uint4* ALO = (uint4*)(sb + OFF_ALO);
#pragma unroll
            for (int rep = 0; rep < 2; rep++) {
                const int slot = wid + rep * 16;
                if (slot < 24) {
                    const int fm = slot / 12, fk = slot % 12;
                    const int rr0 = fm * 16 + quad, rr1 = rr0 + 8;
                    const int cc0 = fk * 16 + 2 * q4, cc1 = cc0 + 8;
                    float2 vv[4];
                    const int rs[2] = {rr0, rr1};
                    const int cs[2] = {cc0, cc1};
#pragma unroll
                    for (int a = 0; a < 4; a++) {
                        const int r = rs[a & 1], cc = cs[a >> 1];
                        const int node = base + r;
                        float2 val = make_float2(0.f, 0.f);
                        if (r < NPC && node < n_nodes && cc < 160) {
                            if (cc < 32) val = *(const float2*)(enc_node + (size_t)node*32 + cc);
                            else         val = *(const float2*)(enc_g + (size_t)node*128 + (cc-32));
                        }
                        vv[a] = val;
                    }
                    uint32_t h[4], l[4];
#pragma unroll
                    for (int a = 0; a < 4; a++) plain_split(vv[a].x, vv[a].y, h[a], l[a]);
                    AHI[slot * 32 + lane] = make_uint4(h[0], h[1], h[2], h[3]);
                    ALO[slot * 32 + lane] = make_uint4(l[0], l[1], l[2], l[3]);
                }
            }
        }
        __syncthreads();

        // ---- ctx GEMM: ctxps[18][256] = ctx @ Wctx + cst3 ----
        {
            const int cwm = wid & 1, cwn = wid >> 1;
            float cacc[4][4];
#pragma unroll
            for (int i = 0; i < 4; i++)
#pragma unroll
                for (int j = 0; j < 4; j++) cacc[i][j] = 0.f;
            const int cnbase = cwn * 32 + 8 * ((lane >> 4) & 1) + (lane & 7);
            mma_loop<6, 4, CB256>(sb, wv + CTXOFF, t, cwm * 12, cnbase, cacc);
            __syncthreads();                    // all ctx MMAs done (race fix)
            prefetch2<CB256>(sb, wv, t);        // L2 chunks fly during epilogue + L1
            // ctx epilogue
            const int rr0 = cwm * 16 + quad;
            const float* cstv = g_cst3[v];
#pragma unroll
            for (int jj = 0; jj < 2; jj++)
#pragma unroll
                for (int e = 0; e < 2; e++) {
                    const int col = cwn * 32 + jj * 16 + e * 8 + 2 * q4;
                    const float2 cst = *(const float2*)(cstv + col);
                    const float* a = cacc[2 * jj + e];
                    if (rr0 < NPC && base + rr0 < n_nodes)
                        *(float2*)(ctxps + rr0 * 260 + col) =
                            make_float2(a[0] + cst.x, a[1] + cst.y);
                    if (rr0 + 8 < NPC && base + rr0 + 8 < n_nodes)
                        *(float2*)(ctxps + (rr0 + 8) * 260 + col) =
                            make_float2(a[2] + cst.x, a[3] + cst.y);
                }
        }

        // ---- L1: produce A frags directly (overlaps L2 weight copies) ----
        {
            uint4* AHI = (uint4*)(sb + OFF_AHI);
            uint4* ALO = (uint4*)(sb + OFF_ALO);
#pragma unroll
            for (int u = 0; u < 8; u++) {
                const int c0 = wn * 128 + 16 * u + 2 * q4;
                const int c2 = c0 + 8;
                float2 a00 = *(const float2*)(b1s + c0);
                float2 a01 = *(const float2*)(b1s + c2);
                float2 a10 = a00, a11 = a01;
#pragma unroll
                for (int q = 0; q < 7; q++) {
                    const float2 w0 = *(const float2*)(W1s + q * 256 + c0);
                    const float2 w2 = *(const float2*)(W1s + q * 256 + c2);
                    ffma2s(a00, sv0[q], w0); ffma2s(a01, sv0[q], w2);
                    ffma2s(a10, sv1[q], w0); ffma2s(a11, sv1[q], w2);
                }
                uint32_t h0, l0, h1, l1, h2, l2, h3, l3;
                relu_split(a00.x, a00.y, h0, l0);
                relu_split(a10.x, a10.y, h1, l1);
                relu_split(a01.x, a01.y, h2, l2);
                relu_split(a11.x, a11.y, h3, l3);
                const int fi = (wm * 16 + 8 * wn + u) * 32 + lane;
                AHI[fi] = make_uint4(h0, h1, h2, h3);
                ALO[fi] = make_uint4(l0, l1, l2, l3);
            }
        }
        __syncthreads();

        const int nbase = wn * 128 + 8 * ((lane >> 4) & 1) + (lane & 7);
        const int nbase4 = wn * 64 + 8 * ((lane >> 4) & 1) + (lane & 7);
        // ---- L2 ----
        {
            float acc[16][4];
#pragma unroll
            for (int i = 0; i < 16; i++)
#pragma unroll
                for (int j = 0; j < 4; j++) acc[i][j] = 0.f;
            mma_loop<8, 16, CB256>(sb, wv, t, wm * 16, nbase, acc);
            __syncthreads();
            prefetch2<CB256>(sb, wv + L3OFF, t);
            epiA<0>(sb, acc, b2s, wm, wn, lane);
        }
        __syncthreads();
        // ---- L3 ----
        {
            float acc[16][4];
#pragma unroll
            for (int i = 0; i < 16; i++)
#pragma unroll
                for (int j = 0; j < 4; j++) acc[i][j] = 0.f;
            mma_loop<8, 16, CB256>(sb, wv + L3OFF, t, wm * 16, nbase, acc);
            __syncthreads();
            prefetch2<CB128>(sb, wv + L4OFF, t);
            epiA<1>(sb, acc, ctxps, wm, wn, lane);
        }
        __syncthreads();
        // ---- L4 + L5 ----
        {
            float acc[8][4];
#pragma unroll
            for (int i = 0; i < 8; i++)
#pragma unroll
                for (int j = 0; j < 4; j++) acc[i][j] = 0.f;
            mma_loop<8, 8, CB128>(sb, wv + L4OFF, t, wm * 16, nbase4, acc);
            __syncthreads();
            if (v + 1 < V_) prefetch2<CB256>(sb, wv + VSTRIDE + CTXOFF, t);
            float s0 = 0.f, s1 = 0.f;
#pragma unroll
            for (int j = 0; j < 8; j++) {
                const int c0 = wn * 64 + 8 * j + 2 * q4;
                const float w30 = w3s[c0], w31 = w3s[c0 + 1];
                const float bb0 = b4s[c0], bb1 = b4s[c0 + 1];
                s0 += fmaxf(acc[j][0] + bb0, 0.f) * w30 + fmaxf(acc[j][1] + bb1, 0.f) * w31;
                s1 += fmaxf(acc[j][2] + bb0, 0.f) * w30 + fmaxf(acc[j][3] + bb1, 0.f) * w31;
            }
            s0 += __shfl_xor_sync(0xffffffffu, s0, 1);
            s0 += __shfl_xor_sync(0xffffffffu, s0, 2);
            s1 += __shfl_xor_sync(0xffffffffu, s1, 1);
            s1 += __shfl_xor_sync(0xffffffffu, s1, 2);
            if (q4 == 0) {
                arowp[wn * 128 + r0m] = s0;
                arowp[wn * 128 + r0m + 8] = s1;
            }
        }
        __syncthreads();
        if (t < 128) arow[t] = arowp[t] + arowp[128 + t] + __ldg(agg_b3 + v);
        __syncthreads();
        if (t < NPC) {
            const int node = base + t;
            if (node < n_nodes) {
                const float c = arow[t * 7];
                float s = 0.f;
#pragma unroll
                for (int j = 0; j < NK; j++) s += arow[t * 7 + 1 + j] * invd[t * 8 + j];
                out[node * V_ + v] = 0.5f * c + 0.5f * s / dsum[t];
            }
        }
        __syncthreads();
    }
}

// ============================ launcher =======================================
extern "C" void kernel_launch(void* const* d_in, const int* in_sizes, int n_in,
                              void* d_out, int out_size)
{
    const float* centers       = (const float*)d_in[0];
    const float* enc_g         = (const float*)d_in[1];
    const float* enc_node      = (const float*)d_in[2];
    const float* neighbors     = (const float*)d_in[3];
    const float* normals       = (const float*)d_in[4];
    const float* neigh_normals = (const float*)d_in[5];
    const float* areas         = (const float*)d_in[6];
    const float* neigh_areas   = (const float*)d_in[7];
    const float* gpv           = (const float*)d_in[8];
    const float* gpr           = (const float*)d_in[9];
    const float* param_W       = (const float*)d_in[10];
    const float* param_b       = (const float*)d_in[11];
    const float* basis_W1      = (const float*)d_in[12];
    const float* basis_b1      = (const float*)d_in[13];
    const float* basis_W2      = (const float*)d_in[14];
    const float* basis_b2      = (const float*)d_in[15];
    const float* agg_W1        = (const float*)d_in[16];
    const float* agg_b1        = (const float*)d_in[17];
    const float* agg_W2        = (const float*)d_in[18];
    const float* agg_b2        = (const float*)d_in[19];
    const float* agg_W3        = (const float*)d_in[20];
    const float* agg_b3        = (const float*)d_in[21];
    float* out = (float*)d_out;

    const int n_nodes = in_sizes[0] / 3;
    const int grid = (n_nodes + NPC - 1) / NPC;

    cudaFuncSetAttribute(surface_kernel,
                         cudaFuncAttributeMaxDynamicSharedMemorySize, SMEM_BYTES);

    cst3_kernel<<<1, 256>>>(gpv, gpr, param_W, param_b, agg_W1, agg_b1);
    wconv_kernel<<<2560, 512>>>(basis_W2, agg_W1, agg_W2);
    surface_kernel<<<grid, NT, SMEM_BYTES>>>(
        centers, enc_g, enc_node, neighbors, normals, neigh_normals,
        areas, neigh_areas,
        basis_W1, basis_b1, basis_b2, agg_b2, agg_W3, agg_b3, out, n_nodes);
}

// round 7
// speedup vs baseline: 2.4514x; 1.0457x over previous
#include <cuda_runtime.h>
#include <cuda_bf16.h>
#include <math.h>
#include <stdint.h>

constexpr int V_ = 4;
constexpr int NK = 6;
constexpr int PP = 7;
constexpr int NPC = 18;
constexpr int ROWS_ = 126;
constexpr int NT = 512;

// weight blob per v, per-warpgroup streams of [128n][64k] (16KB) chunks
// (L4: [64n][64k] 8KB). Per wg: L2 8 chunks, L3 8, L4 8, CTX 6.
constexpr int CB  = 16384;
constexpr int CB4 = 8192;
constexpr int L3OFF  = 16 * CB;               // 262144
constexpr int L4OFF  = L3OFF + 16 * CB;       // 524288
constexpr int CTXOFF = L4OFF + 16 * CB4;      // 655360
constexpr int VSTRIDE = CTXOFF + 12 * CB;     // 851968

__device__ uint8_t g_wB[(size_t)V_ * VSTRIDE];
__device__ float   g_cst3[V_][256];

// ---- smem byte offsets ----
constexpr int OFF_W    = 0;        // 65536: wg0 [0,32K) 2x16K bufs, wg1 [32K,64K)
constexpr int OFF_AHI  = 65536;    // 65536 (A hi frags: 128 slots x 512B)
constexpr int OFF_ALO  = 131072;   // 65536
constexpr int OFF_CTXP = 196608;   // 18*260*4 = 18720
constexpr int OFF_SVOL = 215328;   // 4096
constexpr int OFF_W1S  = 219424;   // 7168
constexpr int OFF_B1S  = 226592;   // 1024
constexpr int OFF_B2S  = 227616;   // 1024
constexpr int OFF_B4S  = 228640;   // 512
constexpr int OFF_W3S  = 229152;   // 512
constexpr int OFF_ARP  = 229664;   // 1024
constexpr int OFF_ARW  = 230688;   // 512
constexpr int OFF_INVD = 231200;   // 576
constexpr int OFF_DSUM = 231776;   // 96
constexpr int SMEM_BYTES = 231872;

// ============================ PTX helpers ====================================
__device__ __forceinline__ uint32_t su32(const void* p) {
    return (uint32_t)__cvta_generic_to_shared(p);
}
__device__ __forceinline__ void cp16(uint8_t* s, const uint8_t* g) {
    uint32_t sa = su32(s);
    asm volatile("cp.async.cg.shared.global [%0], [%1], 16;" :: "r"(sa), "l"(g));
}
#define CP_COMMIT() asm volatile("cp.async.commit_group;" ::: "memory")
#define CP_WAIT1()  asm volatile("cp.async.wait_group 1;" ::: "memory")
#define CP_WAIT0()  asm volatile("cp.async.wait_group 0;" ::: "memory")
// per-warpgroup named barrier (ids 1,2), 256 threads each
#define BARW(g) asm volatile("bar.sync %0, %1;" :: "r"((g) + 1), "r"(256) : "memory")

#define MMA_BF16(acc, a, b0, b1) asm volatile( \
    "mma.sync.aligned.m16n8k16.row.col.f32.bf16.bf16.f32 " \
    "{%0,%1,%2,%3}, {%4,%5,%6,%7}, {%8,%9}, {%0,%1,%2,%3};" \
    : "+f"((acc)[0]), "+f"((acc)[1]), "+f"((acc)[2]), "+f"((acc)[3]) \
    : "r"((a).x), "r"((a).y), "r"((a).z), "r"((a).w), "r"(b0), "r"(b1))

#define LDSM4(r0, r1, r2, r3, addr) asm volatile( \
    "ldmatrix.sync.aligned.m8n8.x4.shared.b16 {%0,%1,%2,%3}, [%4];" \
    : "=r"(r0), "=r"(r1), "=r"(r2), "=r"(r3) : "r"(addr))

__device__ __forceinline__ void relu_split(float x, float y, uint32_t& h, uint32_t& l) {
    x = fmaxf(x, 0.f); y = fmaxf(y, 0.f);
    __nv_bfloat162 hb = __float22bfloat162_rn(make_float2(x, y));
    float2 hf = __bfloat1622float2(hb);
    __nv_bfloat162 lb = __float22bfloat162_rn(make_float2(x - hf.x, y - hf.y));
    h = *reinterpret_cast<uint32_t*>(&hb);
    l = *reinterpret_cast<uint32_t*>(&lb);
}
__device__ __forceinline__ void plain_split(float x, float y, uint32_t& h, uint32_t& l) {
    __nv_bfloat162 hb = __float22bfloat162_rn(make_float2(x, y));
    float2 hf = __bfloat1622float2(hb);
    __nv_bfloat162 lb = __float22bfloat162_rn(make_float2(x - hf.x, y - hf.y));
    h = *reinterpret_cast<uint32_t*>(&hb);
    l = *reinterpret_cast<uint32_t*>(&lb);
}
__device__ __forceinline__ void ffma2s(float2& d, float a, float2 b) {
    unsigned long long dd = *reinterpret_cast<unsigned long long*>(&d);
    float2 av = make_float2(a, a);
    unsigned long long aa = *reinterpret_cast<unsigned long long*>(&av);
    unsigned long long bb = *reinterpret_cast<unsigned long long*>(&b);
    asm("fma.rn.f32x2 %0, %1, %2, %0;" : "+l"(dd) : "l"(aa), "l"(bb));
    d = *reinterpret_cast<float2*>(&dd);
}

// ===================== side kernel 1: cst3 ===================================
__global__ void cst3_kernel(const float* __restrict__ gpv, const float* __restrict__ gpr,
                            const float* __restrict__ pW, const float* __restrict__ pb,
                            const float* __restrict__ aW1, const float* __restrict__ ab1)
{
    __shared__ float pe[32];
    const int t = threadIdx.x;
    const float p0 = gpv[0] / gpr[0], p1 = gpv[1] / gpr[1];
    if (t < 32) pe[t] = fmaxf(pb[t] + p0 * pW[t] + p1 * pW[32 + t], 0.f);
    __syncthreads();
    for (int idx = t; idx < V_ * 256; idx += blockDim.x) {
        const int v = idx >> 8, c = idx & 255;
        const float* W = aW1 + ((size_t)v * 448 + 416) * 256 + c;
        float s = ab1[v * 256 + c];
#pragma unroll
        for (int k = 0; k < 32; k++) s += pe[k] * W[(size_t)k * 256];
        g_cst3[v][c] = s;
    }
}

// ===================== side kernel 2: weight convert =========================
// chunk rows n_local, 128B/row; swizzle byte = n_local*128 + ((2kl)^((n_local&7)<<4))
__global__ void wconv_kernel(const float* __restrict__ bW2,
                             const float* __restrict__ aW1,
                             const float* __restrict__ aW2)
{
    constexpr int PERV = 131072 + 131072 + 65536 + 98304;   // 425984
    const int total = V_ * PERV;
    for (int idx = blockIdx.x * blockDim.x + threadIdx.x; idx < total;
         idx += gridDim.x * blockDim.x) {
        const int v = idx / PERV;
        int e = idx % PERV;
        size_t dst;
        int n_local, kl;
        bool hiC;
        float w;
        if (e < 131072) {                       // L2
            const int wg = e >> 16, r = e & 65535;
            const int c = r >> 13, rr = r & 8191;
            n_local = rr >> 6; kl = rr & 63;
            const int n = wg * 128 + n_local, k = (c & 3) * 64 + kl;
            hiC = (c < 4);
            w = bW2[((size_t)v * 256 + k) * 256 + n];
            dst = (size_t)wg * 8 * CB + (size_t)c * CB;
        } else if (e < 262144) {                // L3
            e -= 131072;
            const int wg = e >> 16, r = e & 65535;
            const int c = r >> 13, rr = r & 8191;
            n_local = rr >> 6; kl = rr & 63;
            const int n = wg * 128 + n_local, k = (c & 3) * 64 + kl;
            hiC = (c < 4);
            w = aW1[((size_t)v * 448 + k) * 256 + n];
            dst = L3OFF + (size_t)wg * 8 * CB + (size_t)c * CB;
        } else if (e < 327680) {                // L4
            e -= 262144;
            const int wg = e >> 15, r = e & 32767;
            const int c = r >> 12, rr = r & 4095;
            n_local = rr >> 6; kl = rr & 63;
            const int n = wg * 64 + n_local, k = (c & 3) * 64 + kl;
            hiC = (c < 4);
            w = aW2[((size_t)v * 256 + k) * 128 + n];
            dst = L4OFF + (size_t)wg * 8 * CB4 + (size_t)c * CB4;
        } else {                                // CTX (K padded 160->192)
            e -= 327680;
            const int wg = e >> 15, r = e & 32767;   // 49152/wg? no: 98304/2=49152
            // careful: 49152 per wg = 6 chunks x 8192
            const int e2 = (e & 32767) | 0;  (void)e2;
            const int wg2 = e / 49152, r2 = e % 49152;
            const int c = r2 >> 13, rr = r2 & 8191;
            n_local = rr >> 6; kl = rr & 63;
            const int n = wg2 * 128 + n_local, k = (c % 3) * 64 + kl;
            hiC = (c < 3);
            w = (k < 160) ? aW1[((size_t)v * 448 + 256 + k) * 256 + n] : 0.f;
            dst = CTXOFF + (size_t)wg2 * 6 * CB + (size_t)c * CB;
            (void)wg; (void)r;
        }
        __nv_bfloat16 hi = __float2bfloat16_rn(w);
        __nv_bfloat16 val = hiC ? hi : __float2bfloat16_rn(w - __bfloat162float(hi));
        uint8_t* p = g_wB + (size_t)v * VSTRIDE + dst
                   + n_local * 128 + (((uint32_t)(kl * 2)) ^ (((uint32_t)n_local & 7) << 4));
        *reinterpret_cast<__nv_bfloat16*>(p) = val;
    }
}

// ===================== per-wg prefetch + mainloop ============================
template <int CBT>
__device__ __forceinline__ void prefetch_wg(uint8_t* sb, const uint8_t* wsrc,
                                            int tw, int wg) {
    constexpr int NCP = CBT / 16 / 256;
    uint8_t* w0 = sb + OFF_W + wg * 32768;
#pragma unroll
    for (int i = 0; i < NCP; i++)
        cp16(w0 + (tw + i * 256) * 16, wsrc + (size_t)(tw + i * 256) * 16);
    CP_COMMIT();
#pragma unroll
    for (int i = 0; i < NCP; i++)
        cp16(w0 + CBT + (tw + i * 256) * 16, wsrc + CBT + (size_t)(tw + i * 256) * 16);
    CP_COMMIT();
}

// requires prefetch_wg<CBT>(wsrc) already issued (2 groups pending).
template <int NCHUNK, int NFRAG, int CBT>
__device__ __forceinline__ void mma_loop_wg(
    uint8_t* sb, const uint8_t* wsrc, int tw, int wg, int lane,
    int aslot0, int nbase, float (*acc)[4])
{
    uint8_t* w0 = sb + OFF_W + wg * 32768;
    const uint4* AHI = (const uint4*)(sb + OFF_AHI);
    const uint4* ALO = (const uint4*)(sb + OFF_ALO);
    const uint32_t swzc = ((uint32_t)lane & 7) << 4;
    const int kadd = ((lane >> 3) & 1) * 8;
    constexpr int NCP = CBT / 16 / 256;
#pragma unroll 1
    for (int c = 0; c < NCHUNK; c++) {
        if (c < NCHUNK - 1) CP_WAIT1(); else CP_WAIT0();
        BARW(wg);
        const uint32_t wb = su32(w0 + (c & 1) * CBT);
        const bool hiB = (c < NCHUNK / 2);
        const int fkb = (c % (NCHUNK / 2)) * 4;
#pragma unroll
        for (int s = 0; s < 4; s++) {
            const int fk = fkb + s;
            const uint4 ah = AHI[(aslot0 + fk) * 32 + lane];
            uint4 al = make_uint4(0, 0, 0, 0);
            if (hiB) al = ALO[(aslot0 + fk) * 32 + lane];
            const int koff = s * 16 + kadd;
            const uint32_t ba = wb + (uint32_t)(nbase * 128)
                              + (((uint32_t)(koff * 2)) ^ swzc);
#pragma unroll
            for (int jj = 0; jj < NFRAG / 2; jj++) {
                uint32_t b0, b1, b2, b3;
                LDSM4(b0, b1, b2, b3, ba + jj * 2048);
                MMA_BF16(acc[2 * jj],     ah, b0, b1);
                MMA_BF16(acc[2 * jj + 1], ah, b2, b3);
                if (hiB) {
                    MMA_BF16(acc[2 * jj],     al, b0, b1);
                    MMA_BF16(acc[2 * jj + 1], al, b2, b3);
                }
            }
        }
        BARW(wg);
        if (c + 2 < NCHUNK) {
#pragma unroll
            for (int i = 0; i < NCP; i++)
                cp16(w0 + (c & 1) * CBT + (tw + i * 256) * 16,
                     wsrc + (size_t)(c + 2) * CBT + (size_t)(tw + i * 256) * 16);
            CP_COMMIT();
        }
    }
}

// ===================== epilogue: C frags -> A frags =========================
// wn here = warpgroup id (column half). MODE 0: bias; MODE 1: per-node ctxp.
template <int MODE>
__device__ __forceinline__ void epiA(
    uint8_t* sb, float (*acc)[4], const float* __restrict__ addv,
    int wm, int wn, int lane)
{
    uint4* AHI = (uint4*)(sb + OFF_AHI);
    uint4* ALO = (uint4*)(sb + OFF_ALO);
    const int quad = lane >> 2, q4 = lane & 3;
    const int r0 = 16 * wm + quad;
    int n0 = r0 / 7;       if (n0 > 17) n0 = 17;
    int n1 = (r0 + 8) / 7; if (n1 > 17) n1 = 17;
#pragma unroll
    for (int u = 0; u < 8; u++) {
        const int c0 = wn * 128 + 16 * u + 2 * q4;
        const int c2 = c0 + 8;
        float2 a00, a01, a10, a11;
        if constexpr (MODE == 0) {
            a00 = *(const float2*)(addv + c0);
            a01 = *(const float2*)(addv + c2);
            a10 = a00; a11 = a01;
        } else {
            a00 = *(const float2*)(addv + n0 * 260 + c0);
            a01 = *(const float2*)(addv + n0 * 260 + c2);
            a10 = *(const float2*)(addv + n1 * 260 + c0);
            a11 = *(const float2*)(addv + n1 * 260 + c2);
        }
        uint32_t h0, l0, h1, l1, h2, l2, h3, l3;
        relu_split(acc[2*u][0]   + a00.x, acc[2*u][1]   + a00.y, h0, l0);
        relu_split(acc[2*u][2]   + a10.x, acc[2*u][3]   + a10.y, h1, l1);
        relu_split(acc[2*u+1][0] + a01.x, acc[2*u+1][1] + a01.y, h2, l2);
        relu_split(acc[2*u+1][2] + a11.x, acc[2*u+1][3] + a11.y, h3, l3);
        const int fi = (wm * 16 + 8 * wn + u) * 32 + lane;
        AHI[fi] = make_uint4(h0, h1, h2, h3);
        ALO[fi] = make_uint4(l0, l1, l2, l3);
    }
}

// ============================ main kernel ====================================
__global__ void __launch_bounds__(NT, 1)
surface_kernel(
    const float* __restrict__ centers,  const float* __restrict__ enc_g,
    const float* __restrict__ enc_node, const float* __restrict__ neighbors,
    const float* __restrict__ normals,  const float* __restrict__ neigh_normals,
    const float* __restrict__ areas,    const float* __restrict__ neigh_areas,
    const float* __restrict__ basis_W1, const float* __restrict__ basis_b1,
    const float* __restrict__ basis_b2, const float* __restrict__ agg_b2,
    const float* __restrict__ agg_W3,   const float* __restrict__ agg_b3,
    float* __restrict__ out, const int n_nodes)
{
    extern __shared__ uint8_t sb[];
    const int t = threadIdx.x;
    const int wid = t >> 5, lane = t & 31;
    const int wg = t >> 8;             // warpgroup 0/1 == column half
    const int tw = t & 255;            // thread index within wg
    const int widg = wid & 7;          // warp within wg == wm
    const int quad = lane >> 2, q4 = lane & 3;
    const int base = blockIdx.x * NPC;

    float* ctxps = (float*)(sb + OFF_CTXP);
    float* svol  = (float*)(sb + OFF_SVOL);
    float* W1s   = (float*)(sb + OFF_W1S);
    float* b1s   = (float*)(sb + OFF_B1S);
    float* b2s   = (float*)(sb + OFF_B2S);
    float* b4s   = (float*)(sb + OFF_B4S);
    float* w3s   = (float*)(sb + OFF_W3S);
    float* arowp = (float*)(sb + OFF_ARP);
    float* arow  = (float*)(sb + OFF_ARW);
    float* invd  = (float*)(sb + OFF_INVD);
    float* dsum  = (float*)(sb + OFF_DSUM);

    // prefetch v=0 ctx chunks (per wg stream)
    prefetch_wg<CB>(sb, g_wB + CTXOFF + (size_t)wg * 6 * CB, tw, wg);

    // ---- build vol rows ----
    if (t < 128) {
        float f[8] = {0.f,0.f,0.f,0.f,0.f,0.f,0.f,0.f};
        const int nl = t / PP, p = t % PP;
        const int node = base + nl;
        if (t < ROWS_ && node < n_nodes) {
            if (p == 0) {
                f[0]=centers[node*3+0]; f[1]=centers[node*3+1]; f[2]=centers[node*3+2];
                f[3]=normals[node*3+0]; f[4]=normals[node*3+1]; f[5]=normals[node*3+2];
                f[6]=logf(areas[node]) * 0.1f;
            } else {
                const int nb = node * NK + (p - 1);
                f[0]=neighbors[nb*3+0]+1e-6f; f[1]=neighbors[nb*3+1]+1e-6f;
                f[2]=neighbors[nb*3+2]+1e-6f;
                f[3]=neigh_normals[nb*3+0]+1e-6f; f[4]=neigh_normals[nb*3+1]+1e-6f;
                f[5]=neigh_normals[nb*3+2]+1e-6f;
                f[6]=logf(neigh_areas[nb]) * 0.1f + 1e-6f;
            }
        }
#pragma unroll
        for (int q = 0; q < 8; q++) svol[t * 8 + q] = f[q];
    }
    __syncthreads();
    if (t < NPC * NK) {
        const int nl = t / NK, j = t % NK;
        float d2 = 0.f;
#pragma unroll
        for (int q = 0; q < 7; q++) {
            const float d = svol[(nl*7)*8 + q] - svol[(nl*7 + 1 + j)*8 + q];
            d2 += d * d;
        }
        invd[nl * 8 + j] = 1.f / sqrtf(d2);
    }
    __syncthreads();
    if (t < NPC) {
        float s = 0.f;
#pragma unroll
        for (int j = 0; j < NK; j++) s += invd[t * 8 + j];
        dsum[t] = s;
    }

    const int r0m = 16 * widg + quad;
    float sv0[7], sv1[7];
#pragma unroll
    for (int q = 0; q < 7; q++) {
        sv0[q] = svol[r0m * 8 + q];
        sv1[q] = svol[(r0m + 8) * 8 + q];
    }

#pragma unroll 1
    for (int v = 0; v < V_; v++) {
        const uint8_t* wv = g_wB + (size_t)v * VSTRIDE;
        // per-v constants
        for (int i = t; i < 1792; i += NT) W1s[i] = __ldg(basis_W1 + (size_t)v * 1792 + i);
        if (t < 256) { b1s[t] = __ldg(basis_b1 + v * 256 + t);
                       b2s[t] = __ldg(basis_b2 + v * 256 + t); }
        else if (t < 384) { b4s[t-256] = __ldg(agg_b2 + v * 128 + (t-256)); }
        else { w3s[t-384] = __ldg(agg_W3 + v * 128 + (t-384)); }

        // ---- build ctx A frags (full CTA; M=32, K padded to 192) ----
        {
            uint4* AHI = (uint4*)(sb + OFF_AHI);
            uint4* ALO = (uint4*)(sb + OFF_ALO);
#pragma unroll
            for (int rep = 0; rep < 2; rep++) {
                const int slot = wid + rep * 16;
                if (slot < 24) {
                    const int fm = slot / 12, fk = slot % 12;
                    const int rr0 = fm * 16 + quad, rr1 = rr0 + 8;
                    const int cc0 = fk * 16 + 2 * q4, cc1 = cc0 + 8;
                    float2 vv[4];
                    const int rs[2] = {rr0, rr1};
                    const int cs[2] = {cc0, cc1};
#pragma unroll
                    for (int a = 0; a < 4; a++) {
                        const int r = rs[a & 1], cc = cs[a >> 1];
                        const int node = base + r;
                        float2 val = make_float2(0.f, 0.f);
                        if (r < NPC && node < n_nodes && cc < 160) {
                            if (cc < 32) val = *(const float2*)(enc_node + (size_t)node*32 + cc);
                            else         val = *(const float2*)(enc_g + (size_t)node*128 + (cc-32));
                        }
                        vv[a] = val;
                    }
                    uint32_t h[4], l[4];
#pragma unroll
                    for (int a = 0; a < 4; a++) plain_split(vv[a].x, vv[a].y, h[a], l[a]);
                    AHI[slot * 32 + lane] = make_uint4(h[0], h[1], h[2], h[3]);
                    ALO[slot * 32 + lane] = make_uint4(l[0], l[1], l[2], l[3]);
                }
            }
        }
        __syncthreads();

        // ---- ctx GEMM: ctxps[18][wg cols] = ctx @ Wctx + cst3 ----
        {
            const int cwm = widg & 1, cwn = widg >> 1;     // 2m x 4n within wg
            float cacc[4][4];
#pragma unroll
            for (int i = 0; i < 4; i++)
#pragma unroll
                for (int j = 0; j < 4; j++) cacc[i][j] = 0.f;
            const int cnbase = cwn * 32 + 8 * ((lane >> 4) & 1) + (lane & 7);
            mma_loop_wg<6, 4, CB>(sb, wv + CTXOFF + (size_t)wg * 6 * CB,
                                  tw, wg, lane, cwm * 12, cnbase, cacc);
            prefetch_wg<CB>(sb, wv + (size_t)wg * 8 * CB, tw, wg);   // L2 chunks
            // ctx epilogue (cols disjoint per wg; read later by same wg only)
            const int rr0 = cwm * 16 + quad;
            const float* cstv = g_cst3[v];
#pragma unroll
            for (int jj = 0; jj < 2; jj++)
#pragma unroll
                for (int e = 0; e < 2; e++) {
                    const int col = wg * 128 + cwn * 32 + jj * 16 + e * 8 + 2 * q4;
                    const float2 cst = *(const float2*)(cstv + col);
                    const float* a = cacc[2 * jj + e];
                    if (rr0 < NPC && base + rr0 < n_nodes)
                        *(float2*)(ctxps + rr0 * 260 + col) =
                            make_float2(a[0] + cst.x, a[1] + cst.y);
                    if (rr0 + 8 < NPC && base + rr0 + 8 < n_nodes)
                        *(float2*)(ctxps + (rr0 + 8) * 260 + col) =
                            make_float2(a[2] + cst.x, a[3] + cst.y);
                }
        }
        __syncthreads();   // ctx A slots free; L1 overwrites them

        // ---- L1: produce A frags directly (overlaps L2 weight copies) ----
        {
            uint4* AHI = (uint4*)(sb + OFF_AHI);
            uint4* ALO = (uint4*)(sb + OFF_ALO);
#pragma unroll
            for (int u = 0; u < 8; u++) {
                const int c0 = wg * 128 + 16 * u + 2 * q4;
                const int c2 = c0 + 8;
                float2 a00 = *(const float2*)(b1s + c0);
                float2 a01 = *(const float2*)(b1s + c2);
                float2 a10 = a00, a11 = a01;
#pragma unroll
                for (int q = 0; q < 7; q++) {
                    const float2 w0 = *(const float2*)(W1s + q * 256 + c0);
                    const float2 w2 = *(const float2*)(W1s + q * 256 + c2);
                    ffma2s(a00, sv0[q], w0); ffma2s(a01, sv0[q], w2);
                    ffma2s(a10, sv1[q], w0); ffma2s(a11, sv1[q], w2);
                }
                uint32_t h0, l0, h1, l1, h2, l2, h3, l3;
                relu_split(a00.x, a00.y, h0, l0);
                relu_split(a10.x, a10.y, h1, l1);
                relu_split(a01.x, a01.y, h2, l2);
                relu_split(a11.x, a11.y, h3, l3);
                const int fi = (widg * 16 + 8 * wg + u) * 32 + lane;
                AHI[fi] = make_uint4(h0, h1, h2, h3);
                ALO[fi] = make_uint4(l0, l1, l2, l3);
            }
        }
        __syncthreads();

        const int nbase = 8 * ((lane >> 4) & 1) + (lane & 7);
        // ---- L2 ----
        {
            float acc[16][4];
#pragma unroll
            for (int i = 0; i < 16; i++)
#pragma unroll
                for (int j = 0; j < 4; j++) acc[i][j] = 0.f;
            mma_loop_wg<8, 16, CB>(sb, wv + (size_t)wg * 8 * CB,
                                   tw, wg, lane, widg * 16, nbase, acc);
            prefetch_wg<CB>(sb, wv + L3OFF + (size_t)wg * 8 * CB, tw, wg);
            __syncthreads();   // both wgs done reading L2 A-frags
            epiA<0>(sb, acc, b2s, widg, wg, lane);
        }
        __syncthreads();
        // ---- L3 ----
        {
            float acc[16][4];
#pragma unroll
            for (int i = 0; i < 16; i++)
#pragma unroll
                for (int j = 0; j < 4; j++) acc[i][j] = 0.f;
            mma_loop_wg<8, 16, CB>(sb, wv + L3OFF + (size_t)wg * 8 * CB,
                                   tw, wg, lane, widg * 16, nbase, acc);
            prefetch_wg<CB4>(sb, wv + L4OFF + (size_t)wg * 8 * CB4, tw, wg);
            __syncthreads();
            epiA<1>(sb, acc, ctxps, widg, wg, lane);
        }
        __syncthreads();
        // ---- L4 + L5 ----
        {
            float acc[8][4];
#pragma unroll
            for (int i = 0; i < 8; i++)
#pragma unroll
                for (int j = 0; j < 4; j++) acc[i][j] = 0.f;
            mma_loop_wg<8, 8, CB4>(sb, wv + L4OFF + (size_t)wg * 8 * CB4,
                                   tw, wg, lane, widg * 16, nbase, acc);
            if (v + 1 < V_)
                prefetch_wg<CB>(sb, wv + VSTRIDE + CTXOFF + (size_t)wg * 6 * CB, tw, wg);
            float s0 = 0.f, s1 = 0.f;
#pragma unroll
            for (int j = 0; j < 8; j++) {
                const int c0 = wg * 64 + 8 * j + 2 * q4;
                const float w30 = w3s[c0], w31 = w3s[c0 + 1];
                const float bb0 = b4s[c0], bb1 = b4s[c0 + 1];
                s0 += fmaxf(acc[j][0] + bb0, 0.f) * w30 + fmaxf(acc[j][1] + bb1, 0.f) * w31;
                s1 += fmaxf(acc[j][2] + bb0, 0.f) * w30 + fmaxf(acc[j][3] + bb1, 0.f) * w31;
            }
            s0 += __shfl_xor_sync(0xffffffffu, s0, 1);
            s0 += __shfl_xor_sync(0xffffffffu, s0, 2);
            s1 += __shfl_xor_sync(0xffffffffu, s1, 1);
            s1 += __shfl_xor_sync(0xffffffffu, s1, 2);
            if (q4 == 0) {
                arowp[wg * 128 + r0m] = s0;
                arowp[wg * 128 + r0m + 8] = s1;
            }
        }
        __syncthreads();
        if (t < 128) arow[t] = arowp[t] + arowp[128 + t] + __ldg(agg_b3 + v);
        __syncthreads();
        if (t < NPC) {
            const int node = base + t;
            if (node < n_nodes) {
                const float c = arow[t * 7];
                float s = 0.f;
#pragma unroll
                for (int j = 0; j < NK; j++) s += arow[t * 7 + 1 + j] * invd[t * 8 + j];
                out[node * V_ + v] = 0.5f * c + 0.5f * s / dsum[t];
            }
        }
        __syncthreads();
    }
}

// ============================ launcher =======================================
extern "C" void kernel_launch(void* const* d_in, const int* in_sizes, int n_in,
                              void* d_out, int out_size)
{
    const float* centers       = (const float*)d_in[0];
    const float* enc_g         = (const float*)d_in[1];
    const float* enc_node      = (const float*)d_in[2];
    const float* neighbors     = (const float*)d_in[3];
    const float* normals       = (const float*)d_in[4];
    const float* neigh_normals = (const float*)d_in[5];
    const float* areas         = (const float*)d_in[6];
    const float* neigh_areas   = (const float*)d_in[7];
    const float* gpv           = (const float*)d_in[8];
    const float* gpr           = (const float*)d_in[9];
    const float* param_W       = (const float*)d_in[10];
    const float* param_b       = (const float*)d_in[11];
    const float* basis_W1      = (const float*)d_in[12];
    const float* basis_b1      = (const float*)d_in[13];
    const float* basis_W2      = (const float*)d_in[14];
    const float* basis_b2      = (const float*)d_in[15];
    const float* agg_W1        = (const float*)d_in[16];
    const float* agg_b1        = (const float*)d_in[17];
    const float* agg_W2        = (const float*)d_in[18];
    const float* agg_b2        = (const float*)d_in[19];
    const float* agg_W3        = (const float*)d_in[20];
    const float* agg_b3        = (const float*)d_in[21];
    float* out = (float*)d_out;

    const int n_nodes = in_sizes[0] / 3;
    const int grid = (n_nodes + NPC - 1) / NPC;

    cudaFuncSetAttribute(surface_kernel,
                         cudaFuncAttributeMaxDynamicSharedMemorySize, SMEM_BYTES);

    cst3_kernel<<<1, 256>>>(gpv, gpr, param_W, param_b, agg_W1, agg_b1);
    wconv_kernel<<<2560, 512>>>(basis_W2, agg_W1, agg_W2);
    surface_kernel<<<grid, NT, SMEM_BYTES>>>(
        centers, enc_g, enc_node, neighbors, normals, neigh_normals,
        areas, neigh_areas,
        basis_W1, basis_b1, basis_b2, agg_b2, agg_W3, agg_b3, out, n_nodes);
}